// round 2
// baseline (speedup 1.0000x reference)
#include <cuda_runtime.h>
#include <math.h>

// Problem constants
#define BB   2
#define NH   16
#define LL   2048
#define EE   1024
#define DD   1024
#define HDD  64
#define NDD  33      // 2*CLIP+1
#define BHH  (BB*NH)     // 32
#define MLL  (BB*LL)     // 4096
#define SCALE 0.03125f   // 1/sqrt(1024)

// ---------------------------------------------------------------------------
// Scratch (device globals: the sanctioned no-alloc path)
// ---------------------------------------------------------------------------
__device__ float g_qh[BHH * LL * HDD];     // (bh, l, hd)
__device__ float g_kh[BHH * LL * HDD];
__device__ float g_vh[BHH * LL * HDD];
__device__ float g_p [BHH * LL * NDD];     // rel-score lookup per (row, dist-class)
__device__ float g_w [BHH * LL * NDD];     // attn mass per dist-class
__device__ float g_o [MLL * DD];           // merged-head attention output
__device__ float g_s [134217728];          // (bh, q, k) scores / attn  (512 MiB)

// ---------------------------------------------------------------------------
// GEMM: out = relu(A @ W^T + bias).  A:(4096,1024) K-contig, W:(1024,1024) K-contig.
// MODE 0/1/2: write split-head layout into g_qh/g_kh/g_vh. MODE 3: A=g_o, flat out.
// 128x128x16 tiles, 256 threads, 8x8 per thread.
// ---------------------------------------------------------------------------
template<int MODE>
__global__ void __launch_bounds__(256, 2)
proj_gemm_kernel(const float* __restrict__ A, const float* __restrict__ W,
                 const float* __restrict__ bias, float* __restrict__ outp)
{
    __shared__ float As[16][132];
    __shared__ float Bs[16][132];
    const int K = EE;
    const int tid = threadIdx.x;
    const int tx = tid & 15, ty = tid >> 4;
    const int m0 = blockIdx.y * 128, n0 = blockIdx.x * 128;

    const float* Ap = (MODE == 3) ? g_o : A;
    const float* Abase = Ap + (size_t)m0 * K;
    const float* Wbase = W + (size_t)n0 * K;

    const int lr = tid >> 2;
    const int lk = (tid & 3) * 4;

    float acc[8][8];
    #pragma unroll
    for (int i = 0; i < 8; ++i)
        #pragma unroll
        for (int j = 0; j < 8; ++j) acc[i][j] = 0.f;

    for (int kt = 0; kt < K; kt += 16) {
        #pragma unroll
        for (int hh = 0; hh < 2; ++hh) {
            int r = lr + hh * 64;
            float4 va = *(const float4*)(Abase + (size_t)r * K + kt + lk);
            As[lk+0][r] = va.x; As[lk+1][r] = va.y; As[lk+2][r] = va.z; As[lk+3][r] = va.w;
            float4 vb = *(const float4*)(Wbase + (size_t)r * K + kt + lk);
            Bs[lk+0][r] = vb.x; Bs[lk+1][r] = vb.y; Bs[lk+2][r] = vb.z; Bs[lk+3][r] = vb.w;
        }
        __syncthreads();
        #pragma unroll
        for (int kk = 0; kk < 16; ++kk) {
            float a[8], b[8];
            *(float4*)(a)     = *(const float4*)&As[kk][ty * 8];
            *(float4*)(a + 4) = *(const float4*)&As[kk][ty * 8 + 4];
            *(float4*)(b)     = *(const float4*)&Bs[kk][tx * 8];
            *(float4*)(b + 4) = *(const float4*)&Bs[kk][tx * 8 + 4];
            #pragma unroll
            for (int i = 0; i < 8; ++i)
                #pragma unroll
                for (int j = 0; j < 8; ++j)
                    acc[i][j] = fmaf(a[i], b[j], acc[i][j]);
        }
        __syncthreads();
    }

    #pragma unroll
    for (int i = 0; i < 8; ++i) {
        int m = m0 + ty * 8 + i;
        int bidx = m >> 11;       // / 2048
        int l = m & 2047;
        #pragma unroll
        for (int j = 0; j < 8; ++j) {
            int n = n0 + tx * 8 + j;
            float vv = fmaxf(acc[i][j] + bias[n], 0.f);
            if (MODE == 3) {
                outp[(size_t)m * DD + n] = vv;
            } else {
                size_t idx = (((size_t)(bidx * NH + (n >> 6))) * LL + l) * HDD + (n & 63);
                if (MODE == 0) g_qh[idx] = vv;
                else if (MODE == 1) g_kh[idx] = vv;
                else g_vh[idx] = vv;
            }
        }
    }
}

// ---------------------------------------------------------------------------
// p[row][j] = sum_d qh[row][d] * rel_k[j][d]   (row = bh*L + q)
// ---------------------------------------------------------------------------
__global__ void __launch_bounds__(264)
pcompute_kernel(const float* __restrict__ rel_k)
{
    __shared__ float qs[8 * HDD];      // 8 rows
    __shared__ float rk[NDD * HDD];
    const int tid = threadIdx.y * 33 + threadIdx.x;
    const size_t row0 = (size_t)blockIdx.x * 8;

    for (int idx = tid; idx < NDD * HDD; idx += 264) rk[idx] = rel_k[idx];
    for (int idx = tid; idx < 8 * HDD;  idx += 264) qs[idx] = g_qh[row0 * HDD + idx];
    __syncthreads();

    const int j = threadIdx.x;
    const int r = threadIdx.y;
    float s = 0.f;
    #pragma unroll
    for (int d = 0; d < HDD; ++d)
        s = fmaf(qs[r * HDD + d], rk[j * HDD + d], s);
    g_p[(row0 + r) * NDD + j] = s;
}

// ---------------------------------------------------------------------------
// scores: S[bh][q][k] = (qh.kh + p[bh][q][clip(k-q)+16]) * SCALE
// 128x128 tiles over (q,k), K=64.
// ---------------------------------------------------------------------------
__global__ void __launch_bounds__(256, 2)
scores_kernel()
{
    __shared__ float As[16][132];
    __shared__ float Bs[16][132];
    const int tid = threadIdx.x;
    const int tx = tid & 15, ty = tid >> 4;
    const int bh = blockIdx.z;
    const int q0 = blockIdx.y * 128;
    const int k0 = blockIdx.x * 128;

    const float* Abase = g_qh + ((size_t)bh * LL + q0) * HDD;
    const float* Bbase = g_kh + ((size_t)bh * LL + k0) * HDD;
    const int lr = tid >> 2;
    const int lk = (tid & 3) * 4;

    float acc[8][8];
    #pragma unroll
    for (int i = 0; i < 8; ++i)
        #pragma unroll
        for (int j = 0; j < 8; ++j) acc[i][j] = 0.f;

    #pragma unroll
    for (int kt = 0; kt < HDD; kt += 16) {
        #pragma unroll
        for (int hh = 0; hh < 2; ++hh) {
            int r = lr + hh * 64;
            float4 va = *(const float4*)(Abase + (size_t)r * HDD + kt + lk);
            As[lk+0][r] = va.x; As[lk+1][r] = va.y; As[lk+2][r] = va.z; As[lk+3][r] = va.w;
            float4 vb = *(const float4*)(Bbase + (size_t)r * HDD + kt + lk);
            Bs[lk+0][r] = vb.x; Bs[lk+1][r] = vb.y; Bs[lk+2][r] = vb.z; Bs[lk+3][r] = vb.w;
        }
        __syncthreads();
        #pragma unroll
        for (int kk = 0; kk < 16; ++kk) {
            float a[8], b[8];
            *(float4*)(a)     = *(const float4*)&As[kk][ty * 8];
            *(float4*)(a + 4) = *(const float4*)&As[kk][ty * 8 + 4];
            *(float4*)(b)     = *(const float4*)&Bs[kk][tx * 8];
            *(float4*)(b + 4) = *(const float4*)&Bs[kk][tx * 8 + 4];
            #pragma unroll
            for (int i = 0; i < 8; ++i)
                #pragma unroll
                for (int j = 0; j < 8; ++j)
                    acc[i][j] = fmaf(a[i], b[j], acc[i][j]);
        }
        __syncthreads();
    }

    float* srow_base = g_s + (size_t)bh * LL * LL;
    const float* prow = g_p + (size_t)bh * LL * NDD;
    #pragma unroll
    for (int i = 0; i < 8; ++i) {
        int q = q0 + ty * 8 + i;
        #pragma unroll
        for (int j = 0; j < 8; ++j) {
            int kpos = k0 + tx * 8 + j;
            int dd = kpos - q;
            dd = dd < -16 ? -16 : (dd > 16 ? 16 : dd);
            float vv = (acc[i][j] + prow[q * NDD + dd + 16]) * SCALE;
            srow_base[(size_t)q * LL + kpos] = vv;
        }
    }
}

// ---------------------------------------------------------------------------
// softmax over k (2048) per row + distance-class mass w[row][0..32]
// ---------------------------------------------------------------------------
__global__ void __launch_bounds__(256)
softmax_w_kernel()
{
    const int row = blockIdx.x;            // bh*L + q
    const int q = row & (LL - 1);
    float* srow = g_s + (size_t)row * LL;
    const int tid = threadIdx.x;
    __shared__ float red[256];

    float vals[8];
    float m = -1e30f;
    #pragma unroll
    for (int i = 0; i < 8; ++i) {
        vals[i] = srow[tid + i * 256];
        m = fmaxf(m, vals[i]);
    }
    red[tid] = m; __syncthreads();
    #pragma unroll
    for (int s = 128; s >= 1; s >>= 1) {
        if (tid < s) red[tid] = fmaxf(red[tid], red[tid + s]);
        __syncthreads();
    }
    m = red[0]; __syncthreads();

    float sum = 0.f;
    #pragma unroll
    for (int i = 0; i < 8; ++i) {
        vals[i] = __expf(vals[i] - m);
        sum += vals[i];
    }
    red[tid] = sum; __syncthreads();
    #pragma unroll
    for (int s = 128; s >= 1; s >>= 1) {
        if (tid < s) red[tid] += red[tid + s];
        __syncthreads();
    }
    sum = red[0]; __syncthreads();
    const float inv = 1.f / sum;

    // zero the w row, then fill
    if (tid < NDD) g_w[(size_t)row * NDD + tid] = 0.f;
    __syncthreads();

    float w0 = 0.f, w32 = 0.f;
    #pragma unroll
    for (int i = 0; i < 8; ++i) {
        int k = tid + i * 256;
        float a = vals[i] * inv;
        srow[k] = a;
        int dd = k - q;
        if (dd <= -16)      w0  += a;
        else if (dd >= 16)  w32 += a;
        else                g_w[(size_t)row * NDD + dd + 16] = a;
    }
    red[tid] = w0; __syncthreads();
    #pragma unroll
    for (int s = 128; s >= 1; s >>= 1) {
        if (tid < s) red[tid] += red[tid + s];
        __syncthreads();
    }
    if (tid == 0) g_w[(size_t)row * NDD + 0] = red[0];
    __syncthreads();
    red[tid] = w32; __syncthreads();
    #pragma unroll
    for (int s = 128; s >= 1; s >>= 1) {
        if (tid < s) red[tid] += red[tid + s];
        __syncthreads();
    }
    if (tid == 0) g_w[(size_t)row * NDD + 32] = red[0];
}

// ---------------------------------------------------------------------------
// O[bh][q][d] = sum_k attn*vh + sum_j w[q][j]*rel_v[j][d]; write merged heads.
// Block: 128 q-rows x 64 d (all), K tiles of 16. 256 threads, 8x4 per thread.
// ---------------------------------------------------------------------------
__global__ void __launch_bounds__(256)
outk_kernel(const float* __restrict__ rel_v)
{
    __shared__ float As[16][132];
    __shared__ float Vs[16][64];
    __shared__ float ws[128 * NDD];   // 4224 floats
    __shared__ float rv[NDD * HDD];   // 2112 floats
    const int tid = threadIdx.x;
    const int tx = tid & 15, ty = tid >> 4;
    const int bh = blockIdx.z;
    const int q0 = blockIdx.x * 128;

    const float* Abase = g_s + ((size_t)bh * LL + q0) * LL;
    const float* Vbase = g_vh + (size_t)bh * LL * HDD;

    for (int idx = tid; idx < 128 * NDD; idx += 256)
        ws[idx] = g_w[((size_t)bh * LL + q0) * NDD + idx];
    for (int idx = tid; idx < NDD * HDD; idx += 256)
        rv[idx] = rel_v[idx];

    const int lr = tid >> 2;
    const int lk = (tid & 3) * 4;
    const int vr = tid >> 4;
    const int vc = (tid & 15) * 4;

    float acc[8][4];
    #pragma unroll
    for (int i = 0; i < 8; ++i)
        #pragma unroll
        for (int j = 0; j < 4; ++j) acc[i][j] = 0.f;

    for (int kt = 0; kt < LL; kt += 16) {
        #pragma unroll
        for (int hh = 0; hh < 2; ++hh) {
            int r = lr + hh * 64;
            float4 va = *(const float4*)(Abase + (size_t)r * LL + kt + lk);
            As[lk+0][r] = va.x; As[lk+1][r] = va.y; As[lk+2][r] = va.z; As[lk+3][r] = va.w;
        }
        float4 vv4 = *(const float4*)(Vbase + (size_t)(kt + vr) * HDD + vc);
        *(float4*)&Vs[vr][vc] = vv4;
        __syncthreads();
        #pragma unroll
        for (int kk = 0; kk < 16; ++kk) {
            float a[8], b[4];
            *(float4*)(a)     = *(const float4*)&As[kk][ty * 8];
            *(float4*)(a + 4) = *(const float4*)&As[kk][ty * 8 + 4];
            *(float4*)(b)     = *(const float4*)&Vs[kk][tx * 4];
            #pragma unroll
            for (int i = 0; i < 8; ++i)
                #pragma unroll
                for (int j = 0; j < 4; ++j)
                    acc[i][j] = fmaf(a[i], b[j], acc[i][j]);
        }
        __syncthreads();
    }

    const int bidx = bh >> 4;
    const int h = bh & 15;
    const int d0 = tx * 4;
    #pragma unroll
    for (int i = 0; i < 8; ++i) {
        int qrow = ty * 8 + i;
        int q = q0 + qrow;
        float r0 = acc[i][0], r1 = acc[i][1], r2 = acc[i][2], r3 = acc[i][3];
        for (int jj = 0; jj < NDD; ++jj) {
            float wv = ws[qrow * NDD + jj];
            const float* rvj = &rv[jj * HDD + d0];
            r0 = fmaf(wv, rvj[0], r0);
            r1 = fmaf(wv, rvj[1], r1);
            r2 = fmaf(wv, rvj[2], r2);
            r3 = fmaf(wv, rvj[3], r3);
        }
        float4 o4 = make_float4(r0, r1, r2, r3);
        *(float4*)&g_o[((size_t)bidx * LL + q) * DD + h * HDD + d0] = o4;
    }
}

// ---------------------------------------------------------------------------
// Launch
// ---------------------------------------------------------------------------
extern "C" void kernel_launch(void* const* d_in, const int* in_sizes, int n_in,
                              void* d_out, int out_size)
{
    const float* q     = (const float*)d_in[0];
    const float* k     = (const float*)d_in[1];
    const float* v     = (const float*)d_in[2];
    const float* Wq    = (const float*)d_in[3];
    const float* bq    = (const float*)d_in[4];
    const float* Wk    = (const float*)d_in[5];
    const float* bk    = (const float*)d_in[6];
    const float* Wv    = (const float*)d_in[7];
    const float* bv    = (const float*)d_in[8];
    const float* Wo    = (const float*)d_in[9];
    const float* bo    = (const float*)d_in[10];
    const float* rel_k = (const float*)d_in[11];
    const float* rel_v = (const float*)d_in[12];
    float* out = (float*)d_out;

    dim3 gproj(DD / 128, MLL / 128);             // (8, 32)
    proj_gemm_kernel<0><<<gproj, 256>>>(q, Wq, bq, nullptr);
    proj_gemm_kernel<1><<<gproj, 256>>>(k, Wk, bk, nullptr);
    proj_gemm_kernel<2><<<gproj, 256>>>(v, Wv, bv, nullptr);

    pcompute_kernel<<<BHH * LL / 8, dim3(33, 8)>>>(rel_k);

    dim3 gsc(LL / 128, LL / 128, BHH);           // (16, 16, 32)
    scores_kernel<<<gsc, 256>>>();

    softmax_w_kernel<<<BHH * LL, 256>>>();

    dim3 gout(LL / 128, 1, BHH);                 // (16, 1, 32)
    outk_kernel<<<gout, 256>>>(rel_v);

    proj_gemm_kernel<3><<<gproj, 256>>>(nullptr, Wo, bo, out);
}

// round 4
// speedup vs baseline: 2.2099x; 2.2099x over previous
#include <cuda_runtime.h>
#include <cstdint>
#include <math.h>

#define BB   2
#define NH   16
#define LL   2048
#define EE   1024
#define DD   1024
#define HDD  64
#define NDD  33
#define BHH  (BB*NH)
#define MLL  (BB*LL)
#define SCALE 0.03125f
#define LDA  36          // smem pitch (floats): conflict-free fragment loads

__device__ float g_qh[BHH * LL * HDD];
__device__ float g_kh[BHH * LL * HDD];
__device__ float g_vt[BHH * HDD * LL];    // transposed V: (bh, hd, l)
__device__ float g_p [BHH * LL * NDD];
__device__ float g_w [BHH * LL * NDD];
__device__ float g_o [MLL * DD];
__device__ float g_s [134217728];

#define SMEM_BYTES 73728   // 2 stages * (128+128)*36 floats * 4B

static __device__ __forceinline__ uint32_t tf32r(float x) {
    uint32_t y; asm("cvt.rna.tf32.f32 %0, %1;" : "=r"(y) : "f"(x)); return y;
}

#define MMA8(c, a, b) \
    asm volatile("mma.sync.aligned.m16n8k8.row.col.f32.tf32.tf32.f32 " \
        "{%0,%1,%2,%3}, {%4,%5,%6,%7}, {%8,%9}, {%0,%1,%2,%3};" \
        : "+f"((c)[0]), "+f"((c)[1]), "+f"((c)[2]), "+f"((c)[3]) \
        : "r"((a)[0]), "r"((a)[1]), "r"((a)[2]), "r"((a)[3]), "r"((b)[0]), "r"((b)[1]))

static __device__ __forceinline__ void sts4(float* p, float4 v) {
    float4 o;
    o.x = __uint_as_float(tf32r(v.x));
    o.y = __uint_as_float(tf32r(v.y));
    o.z = __uint_as_float(tf32r(v.z));
    o.w = __uint_as_float(tf32r(v.w));
    *(float4*)p = o;
}

// One 32-K tile of warp MMAs. A 128 rows, B (NTN*8*4) warp cols. Frag map (m16n8k8 tf32):
// a0=(g,t4) a1=(g+8,t4) a2=(g,t4+4) a3=(g+8,t4+4); b0=(k=t4,n=g) b1=(k=t4+4,n=g)
template<int NTN>
static __device__ __forceinline__ void mma_tile(const float* sA, const float* sB,
    int wm, int wn, int g, int t4, float c[][NTN][4])
{
    #pragma unroll
    for (int ks = 0; ks < 4; ++ks) {
        const int kk = ks * 8;
        uint32_t a[4][4], b[NTN][2];
        #pragma unroll
        for (int mt = 0; mt < 4; ++mt) {
            const float* p = sA + (wm * 64 + mt * 16 + g) * LDA + kk + t4;
            a[mt][0] = __float_as_uint(p[0]);
            a[mt][1] = __float_as_uint(p[8 * LDA]);
            a[mt][2] = __float_as_uint(p[4]);
            a[mt][3] = __float_as_uint(p[8 * LDA + 4]);
        }
        #pragma unroll
        for (int nt = 0; nt < NTN; ++nt) {
            const float* p = sB + (wn * (NTN * 8) + nt * 8 + g) * LDA + kk + t4;
            b[nt][0] = __float_as_uint(p[0]);
            b[nt][1] = __float_as_uint(p[4]);
        }
        #pragma unroll
        for (int mt = 0; mt < 4; ++mt)
            #pragma unroll
            for (int nt = 0; nt < NTN; ++nt)
                MMA8(c[mt][nt], a[mt], b[nt]);
    }
}

// Double-buffered mainloop: C(128 x NTN*32... warp-tiled) += A(128 x K) @ B(RB x K)^T
// K = NT*32. BF4B = RB*32/1024 float4 prefetches per thread.
template<int RB, int NTN, int BF4B>
static __device__ __forceinline__ void gemm_loop(const float* __restrict__ Ag, int lda,
    const float* __restrict__ Bg, int ldb, int NT, float* sm, float c[][NTN][4],
    int tid, int wm, int wn, int g, int t4)
{
    const int stageF = (128 + RB) * LDA;
    float* sA0 = sm;               float* sB0 = sm + 128 * LDA;
    float* sA1 = sm + stageF;      float* sB1 = sm + stageF + 128 * LDA;

    #pragma unroll
    for (int i = 0; i < 4; ++i) {
        int idx = tid + i * 256, r = idx >> 3, c4 = (idx & 7) * 4;
        sts4(sA0 + r * LDA + c4, *(const float4*)(Ag + (size_t)r * lda + c4));
    }
    #pragma unroll
    for (int i = 0; i < BF4B; ++i) {
        int idx = tid + i * 256, r = idx >> 3, c4 = (idx & 7) * 4;
        sts4(sB0 + r * LDA + c4, *(const float4*)(Bg + (size_t)r * ldb + c4));
    }
    __syncthreads();

    for (int t = 0; t < NT; ++t) {
        float* sA = (t & 1) ? sA1 : sA0;
        float* sB = (t & 1) ? sB1 : sB0;
        float4 pa[4], pb[BF4B];
        const bool more = (t + 1 < NT);
        if (more) {
            const int kt = (t + 1) * 32;
            #pragma unroll
            for (int i = 0; i < 4; ++i) {
                int idx = tid + i * 256, r = idx >> 3, c4 = (idx & 7) * 4;
                pa[i] = *(const float4*)(Ag + (size_t)r * lda + kt + c4);
            }
            #pragma unroll
            for (int i = 0; i < BF4B; ++i) {
                int idx = tid + i * 256, r = idx >> 3, c4 = (idx & 7) * 4;
                pb[i] = *(const float4*)(Bg + (size_t)r * ldb + kt + c4);
            }
        }
        mma_tile<NTN>(sA, sB, wm, wn, g, t4, c);
        if (more) {
            float* dA = (t & 1) ? sA0 : sA1;
            float* dB = (t & 1) ? sB0 : sB1;
            #pragma unroll
            for (int i = 0; i < 4; ++i) {
                int idx = tid + i * 256, r = idx >> 3, c4 = (idx & 7) * 4;
                sts4(dA + r * LDA + c4, pa[i]);
            }
            #pragma unroll
            for (int i = 0; i < BF4B; ++i) {
                int idx = tid + i * 256, r = idx >> 3, c4 = (idx & 7) * 4;
                sts4(dB + r * LDA + c4, pb[i]);
            }
        }
        __syncthreads();
    }
}

// Stage accumulator fragments into smem (pitch P) for coalesced writes
template<int NTN, int P>
static __device__ __forceinline__ void frag_to_epi(float* epi, float c[][NTN][4],
    int wm, int wn, int g, int t4)
{
    #pragma unroll
    for (int mt = 0; mt < 4; ++mt)
        #pragma unroll
        for (int nt = 0; nt < NTN; ++nt) {
            int r = wm * 64 + mt * 16 + g;
            int cc = wn * (NTN * 8) + nt * 8 + t4 * 2;
            *(float2*)&epi[r * P + cc]       = make_float2(c[mt][nt][0], c[mt][nt][1]);
            *(float2*)&epi[(r + 8) * P + cc] = make_float2(c[mt][nt][2], c[mt][nt][3]);
        }
}

// ---------------------------------------------------------------------------
// Projections: relu(A @ W^T + b). MODE 0->g_qh 1->g_kh 2->g_vt(transposed) 3: g_o->outp
// ---------------------------------------------------------------------------
template<int MODE>
__global__ void __launch_bounds__(256)
proj_tc(const float* __restrict__ A, const float* __restrict__ W,
        const float* __restrict__ bias, float* __restrict__ outp)
{
    extern __shared__ float sm[];
    const int tid = threadIdx.x, wid = tid >> 5, lane = tid & 31;
    const int wm = wid >> 2, wn = wid & 3, g = lane >> 2, t4 = lane & 3;
    const int n0 = blockIdx.x * 128, m0 = blockIdx.y * 128;
    const float* Ap = (MODE == 3) ? g_o : A;

    float c[4][4][4];
    #pragma unroll
    for (int i = 0; i < 4; ++i)
        #pragma unroll
        for (int j = 0; j < 4; ++j)
            #pragma unroll
            for (int e = 0; e < 4; ++e) c[i][j][e] = 0.f;

    gemm_loop<128, 4, 4>(Ap + (size_t)m0 * EE, EE, W + (size_t)n0 * EE, EE, 32,
                         sm, c, tid, wm, wn, g, t4);

    float* epi = sm;  // pitch 132, reuses stage area (all warps past final sync)
    frag_to_epi<4, 132>(epi, c, wm, wn, g, t4);
    __syncthreads();

    const int bidx = m0 >> 11, l0 = m0 & (LL - 1);
    if (MODE == 2) {
        const int bh0 = bidx * NH + (n0 >> 6);
        for (int idx = tid; idx < 128 * 128; idx += 256) {
            int r = idx & 127, cc = idx >> 7;
            float v = fmaxf(epi[r * 132 + cc] + __ldg(bias + n0 + cc), 0.f);
            g_vt[((size_t)(bh0 + (cc >> 6)) * HDD + (cc & 63)) * LL + l0 + r] = v;
        }
    } else {
        for (int idx = tid; idx < 128 * 32; idx += 256) {
            int r = idx >> 5, cc = (idx & 31) * 4;
            int n = n0 + cc;
            float4 v = *(float4*)&epi[r * 132 + cc];
            v.x = fmaxf(v.x + __ldg(bias + n),     0.f);
            v.y = fmaxf(v.y + __ldg(bias + n + 1), 0.f);
            v.z = fmaxf(v.z + __ldg(bias + n + 2), 0.f);
            v.w = fmaxf(v.w + __ldg(bias + n + 3), 0.f);
            if (MODE == 3) {
                *(float4*)(outp + (size_t)(m0 + r) * DD + n) = v;
            } else {
                float* dst = ((MODE == 0) ? g_qh : g_kh) +
                    (((size_t)(bidx * NH + (n >> 6))) * LL + l0 + r) * HDD + (n & 63);
                *(float4*)dst = v;
            }
        }
    }
}

// ---------------------------------------------------------------------------
// p[row][j] = qh[row] . rel_k[j]
// ---------------------------------------------------------------------------
__global__ void __launch_bounds__(264)
pcompute_kernel(const float* __restrict__ rel_k) {
    __shared__ float qs[8 * HDD];
    __shared__ float rk[NDD * HDD];
    const int tid = threadIdx.y * 33 + threadIdx.x;
    const size_t row0 = (size_t)blockIdx.x * 8;
    for (int i = tid; i < NDD * HDD; i += 264) rk[i] = rel_k[i];
    for (int i = tid; i < 8 * HDD;  i += 264) qs[i] = g_qh[row0 * HDD + i];
    __syncthreads();
    const int j = threadIdx.x, r = threadIdx.y;
    float s = 0.f;
    #pragma unroll
    for (int d = 0; d < HDD; ++d) s = fmaf(qs[r * HDD + d], rk[j * HDD + d], s);
    g_p[(row0 + r) * NDD + j] = s;
}

// ---------------------------------------------------------------------------
// Scores: S = (qh @ kh^T + p) * SCALE.  grid (16 k-tile, 16 q-tile, 32 bh)
// ---------------------------------------------------------------------------
__global__ void __launch_bounds__(256)
scores_tc() {
    extern __shared__ float sm[];
    const int tid = threadIdx.x, wid = tid >> 5, lane = tid & 31;
    const int wm = wid >> 2, wn = wid & 3, g = lane >> 2, t4 = lane & 3;
    const int bh = blockIdx.z, q0 = blockIdx.y * 128, k0 = blockIdx.x * 128;

    float c[4][4][4];
    #pragma unroll
    for (int i = 0; i < 4; ++i)
        #pragma unroll
        for (int j = 0; j < 4; ++j)
            #pragma unroll
            for (int e = 0; e < 4; ++e) c[i][j][e] = 0.f;

    gemm_loop<128, 4, 4>(g_qh + ((size_t)bh * LL + q0) * HDD, HDD,
                         g_kh + ((size_t)bh * LL + k0) * HDD, HDD, 2,
                         sm, c, tid, wm, wn, g, t4);

    float* epi = sm;
    frag_to_epi<4, 132>(epi, c, wm, wn, g, t4);
    __syncthreads();

    const float* pb = g_p + (size_t)bh * LL * NDD;
    for (int idx = tid; idx < 128 * 32; idx += 256) {
        int r = idx >> 5, cc = (idx & 31) * 4;
        int q = q0 + r, kp = k0 + cc;
        float4 v = *(float4*)&epi[r * 132 + cc];
        const float* pr = pb + (size_t)q * NDD + 16;
        int d0 = kp - q;     d0 = d0 < -16 ? -16 : (d0 > 16 ? 16 : d0);
        int d1 = kp + 1 - q; d1 = d1 < -16 ? -16 : (d1 > 16 ? 16 : d1);
        int d2 = kp + 2 - q; d2 = d2 < -16 ? -16 : (d2 > 16 ? 16 : d2);
        int d3 = kp + 3 - q; d3 = d3 < -16 ? -16 : (d3 > 16 ? 16 : d3);
        v.x = (v.x + pr[d0]) * SCALE;
        v.y = (v.y + pr[d1]) * SCALE;
        v.z = (v.z + pr[d2]) * SCALE;
        v.w = (v.w + pr[d3]) * SCALE;
        *(float4*)&g_s[((size_t)bh * LL + q) * LL + kp] = v;
    }
}

// ---------------------------------------------------------------------------
// Softmax + distance-class mass
// ---------------------------------------------------------------------------
__global__ void __launch_bounds__(256)
softmax_w_kernel() {
    const int row = blockIdx.x, q = row & (LL - 1), tid = threadIdx.x;
    float* srow = g_s + (size_t)row * LL;
    __shared__ float red[256];
    float vals[8], m = -1e30f;
    #pragma unroll
    for (int i = 0; i < 8; ++i) { vals[i] = srow[tid + i * 256]; m = fmaxf(m, vals[i]); }
    red[tid] = m; __syncthreads();
    #pragma unroll
    for (int s = 128; s >= 1; s >>= 1) { if (tid < s) red[tid] = fmaxf(red[tid], red[tid + s]); __syncthreads(); }
    m = red[0]; __syncthreads();
    float sum = 0.f;
    #pragma unroll
    for (int i = 0; i < 8; ++i) { vals[i] = __expf(vals[i] - m); sum += vals[i]; }
    red[tid] = sum; __syncthreads();
    #pragma unroll
    for (int s = 128; s >= 1; s >>= 1) { if (tid < s) red[tid] += red[tid + s]; __syncthreads(); }
    sum = red[0]; __syncthreads();
    const float inv = 1.f / sum;
    if (tid < NDD) g_w[(size_t)row * NDD + tid] = 0.f;
    __syncthreads();
    float w0 = 0.f, w32 = 0.f;
    #pragma unroll
    for (int i = 0; i < 8; ++i) {
        int k = tid + i * 256;
        float a = vals[i] * inv;
        srow[k] = a;
        int dd = k - q;
        if (dd <= -16) w0 += a;
        else if (dd >= 16) w32 += a;
        else g_w[(size_t)row * NDD + dd + 16] = a;
    }
    red[tid] = w0; __syncthreads();
    #pragma unroll
    for (int s = 128; s >= 1; s >>= 1) { if (tid < s) red[tid] += red[tid + s]; __syncthreads(); }
    if (tid == 0) g_w[(size_t)row * NDD + 0] = red[0];
    __syncthreads();
    red[tid] = w32; __syncthreads();
    #pragma unroll
    for (int s = 128; s >= 1; s >>= 1) { if (tid < s) red[tid] += red[tid + s]; __syncthreads(); }
    if (tid == 0) g_w[(size_t)row * NDD + 32] = red[0];
}

// ---------------------------------------------------------------------------
// Output: O = attn @ vt^T + w @ rel_v. grid (16 q-tile, 1, 32 bh). M=128,N=64,K=2048
// ---------------------------------------------------------------------------
__global__ void __launch_bounds__(256)
outk_tc(const float* __restrict__ rel_v) {
    extern __shared__ float sm[];
    const int tid = threadIdx.x, wid = tid >> 5, lane = tid & 31;
    const int wm = wid >> 2, wn = wid & 3, g = lane >> 2, t4 = lane & 3;
    const int bh = blockIdx.z, q0 = blockIdx.x * 128;

    float c[4][2][4];
    #pragma unroll
    for (int i = 0; i < 4; ++i)
        #pragma unroll
        for (int j = 0; j < 2; ++j)
            #pragma unroll
            for (int e = 0; e < 4; ++e) c[i][j][e] = 0.f;

    gemm_loop<64, 2, 2>(g_s + ((size_t)bh * LL + q0) * LL, LL,
                        g_vt + (size_t)bh * HDD * LL, LL, 64,
                        sm, c, tid, wm, wn, g, t4);

    float* epi = sm;           // pitch 68: 8704 floats
    float* ws  = sm + 8704;    // 128*33 = 4224 floats
    float* rv  = sm + 8704 + 4224;  // 33*64 = 2112 floats
    frag_to_epi<2, 68>(epi, c, wm, wn, g, t4);
    for (int idx = tid; idx < 128 * NDD; idx += 256)
        ws[idx] = g_w[((size_t)bh * LL + q0) * NDD + idx];
    for (int idx = tid; idx < NDD * HDD; idx += 256)
        rv[idx] = rel_v[idx];
    __syncthreads();

    const int bidx = bh >> 4, h = bh & 15;
    for (int idx = tid; idx < 128 * 16; idx += 256) {
        int r = idx >> 4, cc = (idx & 15) * 4;
        float4 acc = *(float4*)&epi[r * 68 + cc];
        const float* wr = ws + r * NDD;
        #pragma unroll 11
        for (int j = 0; j < NDD; ++j) {
            float wv = wr[j];
            const float* rj = rv + j * HDD + cc;
            acc.x = fmaf(wv, rj[0], acc.x);
            acc.y = fmaf(wv, rj[1], acc.y);
            acc.z = fmaf(wv, rj[2], acc.z);
            acc.w = fmaf(wv, rj[3], acc.w);
        }
        *(float4*)&g_o[((size_t)bidx * LL + q0 + r) * DD + h * HDD + cc] = acc;
    }
}

// ---------------------------------------------------------------------------
extern "C" void kernel_launch(void* const* d_in, const int* in_sizes, int n_in,
                              void* d_out, int out_size) {
    const float* q     = (const float*)d_in[0];
    const float* k     = (const float*)d_in[1];
    const float* v     = (const float*)d_in[2];
    const float* Wq    = (const float*)d_in[3];
    const float* bq    = (const float*)d_in[4];
    const float* Wk    = (const float*)d_in[5];
    const float* bk    = (const float*)d_in[6];
    const float* Wv    = (const float*)d_in[7];
    const float* bv    = (const float*)d_in[8];
    const float* Wo    = (const float*)d_in[9];
    const float* bo    = (const float*)d_in[10];
    const float* rel_k = (const float*)d_in[11];
    const float* rel_v = (const float*)d_in[12];
    float* out = (float*)d_out;

    cudaFuncSetAttribute(proj_tc<0>, cudaFuncAttributeMaxDynamicSharedMemorySize, SMEM_BYTES);
    cudaFuncSetAttribute(proj_tc<1>, cudaFuncAttributeMaxDynamicSharedMemorySize, SMEM_BYTES);
    cudaFuncSetAttribute(proj_tc<2>, cudaFuncAttributeMaxDynamicSharedMemorySize, SMEM_BYTES);
    cudaFuncSetAttribute(proj_tc<3>, cudaFuncAttributeMaxDynamicSharedMemorySize, SMEM_BYTES);
    cudaFuncSetAttribute(scores_tc,  cudaFuncAttributeMaxDynamicSharedMemorySize, SMEM_BYTES);
    cudaFuncSetAttribute(outk_tc,    cudaFuncAttributeMaxDynamicSharedMemorySize, SMEM_BYTES);

    dim3 gproj(DD / 128, MLL / 128);                 // (8, 32)
    proj_tc<0><<<gproj, 256, SMEM_BYTES>>>(q, Wq, bq, nullptr);
    proj_tc<1><<<gproj, 256, SMEM_BYTES>>>(k, Wk, bk, nullptr);
    proj_tc<2><<<gproj, 256, SMEM_BYTES>>>(v, Wv, bv, nullptr);

    pcompute_kernel<<<BHH * LL / 8, dim3(33, 8)>>>(rel_k);

    dim3 gsc(LL / 128, LL / 128, BHH);               // (16, 16, 32)
    scores_tc<<<gsc, 256, SMEM_BYTES>>>();

    softmax_w_kernel<<<BHH * LL, 256>>>();

    dim3 gout(LL / 128, 1, BHH);                     // (16, 1, 32)
    outk_tc<<<gout, 256, SMEM_BYTES>>>(rel_v);

    proj_tc<3><<<gproj, 256, SMEM_BYTES>>>(nullptr, Wo, bo, out);
}

// round 7
// speedup vs baseline: 2.8286x; 1.2800x over previous
#include <cuda_runtime.h>
#include <cstdint>
#include <math.h>

#define BB   2
#define NH   16
#define LL   2048
#define EE   1024
#define DD   1024
#define HDD  64
#define NDD  33
#define BHH  (BB*NH)
#define MLL  (BB*LL)
#define SCALE 0.03125f
#define LDA  36          // smem pitch (floats) for 32-wide K tiles

__device__ float g_qh[BHH * LL * HDD];
__device__ float g_kh[BHH * LL * HDD];
__device__ float g_vt[BHH * HDD * LL];    // transposed V: (bh, hd, l)
__device__ float g_p [BHH * LL * NDD];
__device__ float g_o [MLL * DD];

#define SMEM_BYTES 73728   // proj kernels: 2 stages * (128+128)*36 floats * 4B

static __device__ __forceinline__ uint32_t tf32r(float x) {
    uint32_t y; asm("cvt.rna.tf32.f32 %0, %1;" : "=r"(y) : "f"(x)); return y;
}
static __device__ __forceinline__ uint32_t f2u(float x) { return __float_as_uint(x); }

#define MMA8(c, a, b) \
    asm volatile("mma.sync.aligned.m16n8k8.row.col.f32.tf32.tf32.f32 " \
        "{%0,%1,%2,%3}, {%4,%5,%6,%7}, {%8,%9}, {%0,%1,%2,%3};" \
        : "+f"((c)[0]), "+f"((c)[1]), "+f"((c)[2]), "+f"((c)[3]) \
        : "r"((a)[0]), "r"((a)[1]), "r"((a)[2]), "r"((a)[3]), "r"((b)[0]), "r"((b)[1]))

static __device__ __forceinline__ void sts4(float* p, float4 v) {
    float4 o;
    o.x = __uint_as_float(tf32r(v.x));
    o.y = __uint_as_float(tf32r(v.y));
    o.z = __uint_as_float(tf32r(v.z));
    o.w = __uint_as_float(tf32r(v.w));
    *(float4*)p = o;
}

// ------------------- round-4 validated GEMM machinery (projections) --------
template<int NTN>
static __device__ __forceinline__ void mma_tile(const float* sA, const float* sB,
    int wm, int wn, int g, int t4, float c[][NTN][4])
{
    #pragma unroll
    for (int ks = 0; ks < 4; ++ks) {
        const int kk = ks * 8;
        uint32_t a[4][4], b[NTN][2];
        #pragma unroll
        for (int mt = 0; mt < 4; ++mt) {
            const float* p = sA + (wm * 64 + mt * 16 + g) * LDA + kk + t4;
            a[mt][0] = f2u(p[0]); a[mt][1] = f2u(p[8 * LDA]);
            a[mt][2] = f2u(p[4]); a[mt][3] = f2u(p[8 * LDA + 4]);
        }
        #pragma unroll
        for (int nt = 0; nt < NTN; ++nt) {
            const float* p = sB + (wn * (NTN * 8) + nt * 8 + g) * LDA + kk + t4;
            b[nt][0] = f2u(p[0]); b[nt][1] = f2u(p[4]);
        }
        #pragma unroll
        for (int mt = 0; mt < 4; ++mt)
            #pragma unroll
            for (int nt = 0; nt < NTN; ++nt)
                MMA8(c[mt][nt], a[mt], b[nt]);
    }
}

template<int RB, int NTN, int BF4B>
static __device__ __forceinline__ void gemm_loop(const float* __restrict__ Ag, int lda,
    const float* __restrict__ Bg, int ldb, int NT, float* sm, float c[][NTN][4],
    int tid, int wm, int wn, int g, int t4)
{
    const int stageF = (128 + RB) * LDA;
    float* sA0 = sm;               float* sB0 = sm + 128 * LDA;
    float* sA1 = sm + stageF;      float* sB1 = sm + stageF + 128 * LDA;

    #pragma unroll
    for (int i = 0; i < 4; ++i) {
        int idx = tid + i * 256, r = idx >> 3, c4 = (idx & 7) * 4;
        sts4(sA0 + r * LDA + c4, *(const float4*)(Ag + (size_t)r * lda + c4));
    }
    #pragma unroll
    for (int i = 0; i < BF4B; ++i) {
        int idx = tid + i * 256, r = idx >> 3, c4 = (idx & 7) * 4;
        sts4(sB0 + r * LDA + c4, *(const float4*)(Bg + (size_t)r * ldb + c4));
    }
    __syncthreads();

    for (int t = 0; t < NT; ++t) {
        float* sA = (t & 1) ? sA1 : sA0;
        float* sB = (t & 1) ? sB1 : sB0;
        float4 pa[4], pb[BF4B];
        const bool more = (t + 1 < NT);
        if (more) {
            const int kt = (t + 1) * 32;
            #pragma unroll
            for (int i = 0; i < 4; ++i) {
                int idx = tid + i * 256, r = idx >> 3, c4 = (idx & 7) * 4;
                pa[i] = *(const float4*)(Ag + (size_t)r * lda + kt + c4);
            }
            #pragma unroll
            for (int i = 0; i < BF4B; ++i) {
                int idx = tid + i * 256, r = idx >> 3, c4 = (idx & 7) * 4;
                pb[i] = *(const float4*)(Bg + (size_t)r * ldb + kt + c4);
            }
        }
        mma_tile<NTN>(sA, sB, wm, wn, g, t4, c);
        if (more) {
            float* dA = (t & 1) ? sA0 : sA1;
            float* dB = (t & 1) ? sB0 : sB1;
            #pragma unroll
            for (int i = 0; i < 4; ++i) {
                int idx = tid + i * 256, r = idx >> 3, c4 = (idx & 7) * 4;
                sts4(dA + r * LDA + c4, pa[i]);
            }
            #pragma unroll
            for (int i = 0; i < BF4B; ++i) {
                int idx = tid + i * 256, r = idx >> 3, c4 = (idx & 7) * 4;
                sts4(dB + r * LDA + c4, pb[i]);
            }
        }
        __syncthreads();
    }
}

template<int NTN, int P>
static __device__ __forceinline__ void frag_to_epi(float* epi, float c[][NTN][4],
    int wm, int wn, int g, int t4)
{
    #pragma unroll
    for (int mt = 0; mt < 4; ++mt)
        #pragma unroll
        for (int nt = 0; nt < NTN; ++nt) {
            int r = wm * 64 + mt * 16 + g;
            int cc = wn * (NTN * 8) + nt * 8 + t4 * 2;
            *(float2*)&epi[r * P + cc]       = make_float2(c[mt][nt][0], c[mt][nt][1]);
            *(float2*)&epi[(r + 8) * P + cc] = make_float2(c[mt][nt][2], c[mt][nt][3]);
        }
}

// ---------------------------------------------------------------------------
// Projections: relu(A @ W^T + b). MODE 0->g_qh 1->g_kh 2->g_vt(transposed) 3: g_o->outp
// ---------------------------------------------------------------------------
template<int MODE>
__global__ void __launch_bounds__(256)
proj_tc(const float* __restrict__ A, const float* __restrict__ W,
        const float* __restrict__ bias, float* __restrict__ outp)
{
    extern __shared__ float sm[];
    const int tid = threadIdx.x, wid = tid >> 5, lane = tid & 31;
    const int wm = wid >> 2, wn = wid & 3, g = lane >> 2, t4 = lane & 3;
    const int n0 = blockIdx.x * 128, m0 = blockIdx.y * 128;
    const float* Ap = (MODE == 3) ? g_o : A;

    float c[4][4][4];
    #pragma unroll
    for (int i = 0; i < 4; ++i)
        #pragma unroll
        for (int j = 0; j < 4; ++j)
            #pragma unroll
            for (int e = 0; e < 4; ++e) c[i][j][e] = 0.f;

    gemm_loop<128, 4, 4>(Ap + (size_t)m0 * EE, EE, W + (size_t)n0 * EE, EE, 32,
                         sm, c, tid, wm, wn, g, t4);

    float* epi = sm;
    frag_to_epi<4, 132>(epi, c, wm, wn, g, t4);
    __syncthreads();

    const int bidx = m0 >> 11, l0 = m0 & (LL - 1);
    if (MODE == 2) {
        const int bh0 = bidx * NH + (n0 >> 6);
        for (int idx = tid; idx < 128 * 128; idx += 256) {
            int r = idx & 127, cc = idx >> 7;
            float v = fmaxf(epi[r * 132 + cc] + __ldg(bias + n0 + cc), 0.f);
            g_vt[((size_t)(bh0 + (cc >> 6)) * HDD + (cc & 63)) * LL + l0 + r] = v;
        }
    } else {
        for (int idx = tid; idx < 128 * 32; idx += 256) {
            int r = idx >> 5, cc = (idx & 31) * 4;
            int n = n0 + cc;
            float4 v = *(float4*)&epi[r * 132 + cc];
            v.x = fmaxf(v.x + __ldg(bias + n),     0.f);
            v.y = fmaxf(v.y + __ldg(bias + n + 1), 0.f);
            v.z = fmaxf(v.z + __ldg(bias + n + 2), 0.f);
            v.w = fmaxf(v.w + __ldg(bias + n + 3), 0.f);
            if (MODE == 3) {
                *(float4*)(outp + (size_t)(m0 + r) * DD + n) = v;
            } else {
                float* dst = ((MODE == 0) ? g_qh : g_kh) +
                    (((size_t)(bidx * NH + (n >> 6))) * LL + l0 + r) * HDD + (n & 63);
                *(float4*)dst = v;
            }
        }
    }
}

// ---------------------------------------------------------------------------
// p[row][j] = qh[row] . rel_k[j]  — rel_k TRANSPOSED in smem (kills 32-way conflicts)
// ---------------------------------------------------------------------------
__global__ void __launch_bounds__(264)
pcompute_kernel(const float* __restrict__ rel_k) {
    __shared__ float qs[8 * HDD];
    __shared__ float rkT[HDD * 36];
    const int tid = threadIdx.y * 33 + threadIdx.x;
    const size_t row0 = (size_t)blockIdx.x * 8;
    for (int i = tid; i < NDD * HDD; i += 264) {
        int j = i >> 6, d = i & 63;
        rkT[d * 36 + j] = rel_k[i];
    }
    for (int i = tid; i < 8 * HDD; i += 264) qs[i] = g_qh[row0 * HDD + i];
    __syncthreads();
    const int j = threadIdx.x, r = threadIdx.y;
    float s = 0.f;
    #pragma unroll
    for (int d = 0; d < HDD; ++d) s = fmaf(qs[r * HDD + d], rkT[d * 36 + j], s);
    g_p[(row0 + r) * NDD + j] = s;
}

// ---------------------------------------------------------------------------
// Fused flash attention with Shaw relative positions.
// CTA: 128 q rows x one bh; 32 k-tiles of 64. Eliminates g_s / g_w entirely.
// Band trick: for |d|<16 each class j is a single attention element (captured in
// smem, online-rescaled); tails (d<=-16 / d>=16) tracked as two online sums.
// ---------------------------------------------------------------------------
#define F_SQ    0        // 128*68
#define F_SK    8704     // 64*68
#define F_SV    13056    // 64*68
#define F_SP    17408    // 128*68  (P tiles; reused as epilogue staging)
#define F_PS    26112    // 128*36  (p bias)
#define F_BAND  30720    // 128*31
#define F_RV    34688    // 33*64
#define F_ALPHA 36800    // 128
#define F_LROW  36928    // 128
#define F_LO    37056    // 128
#define F_HI    37184    // 128
#define FLASH_SMEM (37312 * 4)

__global__ void __launch_bounds__(256)
flash_tc(const float* __restrict__ rel_v)
{
    extern __shared__ float sm[];
    float* sQ   = sm + F_SQ;
    float* sK   = sm + F_SK;
    float* sV   = sm + F_SV;
    float* sP   = sm + F_SP;
    float* p_s  = sm + F_PS;
    float* band = sm + F_BAND;
    float* rv   = sm + F_RV;
    float* alpha_row = sm + F_ALPHA;
    float* l_row  = sm + F_LROW;
    float* lo_row = sm + F_LO;
    float* hi_row = sm + F_HI;

    const int tid = threadIdx.x, wid = tid >> 5, lane = tid & 31;
    const int g = lane >> 2, t4 = lane & 3;
    const int q0 = blockIdx.x * 128, bh = blockIdx.y;

    // one-time loads
    const float* Qg = g_qh + ((size_t)bh * LL + q0) * HDD;
    #pragma unroll
    for (int i = 0; i < 8; ++i) {
        int idx = tid + i * 256, r = idx >> 4, c4 = (idx & 15) * 4;
        sts4(sQ + r * 68 + c4, *(const float4*)(Qg + (size_t)r * HDD + c4));
    }
    for (int idx = tid; idx < 128 * NDD; idx += 256) {
        int r = idx / 33, j = idx - r * 33;
        p_s[r * 36 + j] = g_p[((size_t)bh * LL + q0 + r) * NDD + j];
    }
    for (int idx = tid; idx < NDD * HDD; idx += 256) rv[idx] = rel_v[idx];
    for (int idx = tid; idx < 128 * 31; idx += 256) band[idx] = 0.f;

    float m_r[2] = { -1e30f, -1e30f }, l_r[2] = { 0.f, 0.f };
    float lo_r[2] = { 0.f, 0.f }, hi_r[2] = { 0.f, 0.f };
    float c_o[4][2][4];
    #pragma unroll
    for (int mt = 0; mt < 4; ++mt)
        #pragma unroll
        for (int nt = 0; nt < 2; ++nt)
            #pragma unroll
            for (int e = 0; e < 4; ++e) c_o[mt][nt][e] = 0.f;

    const float* Kg = g_kh + (size_t)bh * LL * HDD;
    const float* Vg = g_vt + (size_t)bh * HDD * LL;

    for (int kt = 0; kt < 32; ++kt) {
        __syncthreads();
        #pragma unroll
        for (int i = 0; i < 4; ++i) {
            int idx = tid + i * 256, r = idx >> 4, c4 = (idx & 15) * 4;
            sts4(sK + r * 68 + c4, *(const float4*)(Kg + (size_t)(kt * 64 + r) * HDD + c4));
            sts4(sV + r * 68 + c4, *(const float4*)(Vg + (size_t)r * LL + kt * 64 + c4));
        }
        __syncthreads();

        // GEMM1: S(16q x 64k per warp) = Q @ K^T
        float cs[8][4];
        #pragma unroll
        for (int nt = 0; nt < 8; ++nt)
            #pragma unroll
            for (int e = 0; e < 4; ++e) cs[nt][e] = 0.f;
        #pragma unroll
        for (int ks = 0; ks < 8; ++ks) {
            int kk = ks * 8;
            const float* ap = sQ + (wid * 16 + g) * 68 + kk + t4;
            uint32_t a[4] = { f2u(ap[0]), f2u(ap[8 * 68]), f2u(ap[4]), f2u(ap[8 * 68 + 4]) };
            #pragma unroll
            for (int nt = 0; nt < 8; ++nt) {
                const float* bp = sK + (nt * 8 + g) * 68 + kk + t4;
                uint32_t b[2] = { f2u(bp[0]), f2u(bp[4]) };
                MMA8(cs[nt], a, b);
            }
        }

        // online softmax per row-half
        #pragma unroll
        for (int rr = 0; rr < 2; ++rr) {
            const int r = wid * 16 + g + rr * 8;
            const int qg = q0 + r;
            float sv[8][2], mx = -1e30f;
            #pragma unroll
            for (int nt = 0; nt < 8; ++nt)
                #pragma unroll
                for (int e = 0; e < 2; ++e) {
                    int kg = kt * 64 + nt * 8 + t4 * 2 + e;
                    int d = kg - qg;
                    int j = d < -16 ? -16 : (d > 16 ? 16 : d);
                    float v = (cs[nt][rr * 2 + e] + p_s[r * 36 + j + 16]) * SCALE;
                    sv[nt][e] = v;
                    mx = fmaxf(mx, v);
                }
            mx = fmaxf(mx, __shfl_xor_sync(0xffffffffu, mx, 1));
            mx = fmaxf(mx, __shfl_xor_sync(0xffffffffu, mx, 2));
            float mnew = fmaxf(m_r[rr], mx);
            float alpha = __expf(m_r[rr] - mnew);
            m_r[rr] = mnew;
            l_r[rr] *= alpha; lo_r[rr] *= alpha; hi_r[rr] *= alpha;
            for (int j = t4; j < 31; j += 4) band[r * 31 + j] *= alpha;
            __syncwarp();
            if (t4 == 0) alpha_row[r] = alpha;
            float sum = 0.f, slo = 0.f, shi = 0.f;
            #pragma unroll
            for (int nt = 0; nt < 8; ++nt)
                #pragma unroll
                for (int e = 0; e < 2; ++e) {
                    int kg = kt * 64 + nt * 8 + t4 * 2 + e;
                    int d = kg - qg;
                    float p = __expf(sv[nt][e] - mnew);
                    sum += p;
                    if (d <= -16) slo += p;
                    else if (d >= 16) shi += p;
                    else band[r * 31 + d + 15] = p;
                    sP[r * 68 + nt * 8 + t4 * 2 + e] = __uint_as_float(tf32r(p));
                }
            sum += __shfl_xor_sync(0xffffffffu, sum, 1);
            sum += __shfl_xor_sync(0xffffffffu, sum, 2);
            slo += __shfl_xor_sync(0xffffffffu, slo, 1);
            slo += __shfl_xor_sync(0xffffffffu, slo, 2);
            shi += __shfl_xor_sync(0xffffffffu, shi, 1);
            shi += __shfl_xor_sync(0xffffffffu, shi, 2);
            l_r[rr] += sum; lo_r[rr] += slo; hi_r[rr] += shi;
        }
        __syncthreads();

        // rescale output accumulator (rows per GEMM2 layout)
        #pragma unroll
        for (int mt = 0; mt < 4; ++mt) {
            int ro = (wid >> 2) * 64 + mt * 16 + g;
            float a0 = alpha_row[ro], a1 = alpha_row[ro + 8];
            #pragma unroll
            for (int nt = 0; nt < 2; ++nt) {
                c_o[mt][nt][0] *= a0; c_o[mt][nt][1] *= a0;
                c_o[mt][nt][2] *= a1; c_o[mt][nt][3] *= a1;
            }
        }

        // GEMM2: O(64q x 16d per warp) += P @ V
        #pragma unroll
        for (int ks = 0; ks < 8; ++ks) {
            int kk = ks * 8;
            uint32_t b[2][2];
            #pragma unroll
            for (int nt = 0; nt < 2; ++nt) {
                const float* bp = sV + ((wid & 3) * 16 + nt * 8 + g) * 68 + kk + t4;
                b[nt][0] = f2u(bp[0]); b[nt][1] = f2u(bp[4]);
            }
            #pragma unroll
            for (int mt = 0; mt < 4; ++mt) {
                const float* ap = sP + ((wid >> 2) * 64 + mt * 16 + g) * 68 + kk + t4;
                uint32_t a[4] = { f2u(ap[0]), f2u(ap[8 * 68]), f2u(ap[4]), f2u(ap[8 * 68 + 4]) };
                #pragma unroll
                for (int nt = 0; nt < 2; ++nt) MMA8(c_o[mt][nt], a, b[nt]);
            }
        }
    }

    // publish per-row softmax state
    #pragma unroll
    for (int rr = 0; rr < 2; ++rr) {
        int r = wid * 16 + g + rr * 8;
        if (t4 == 0) { l_row[r] = l_r[rr]; lo_row[r] = lo_r[rr]; hi_row[r] = hi_r[rr]; }
    }
    __syncthreads();

    // stage c_o into sP (epilogue staging, pitch 68)
    #pragma unroll
    for (int mt = 0; mt < 4; ++mt)
        #pragma unroll
        for (int nt = 0; nt < 2; ++nt) {
            int r = (wid >> 2) * 64 + mt * 16 + g;
            int cc = (wid & 3) * 16 + nt * 8 + t4 * 2;
            *(float2*)&sP[r * 68 + cc]       = make_float2(c_o[mt][nt][0], c_o[mt][nt][1]);
            *(float2*)&sP[(r + 8) * 68 + cc] = make_float2(c_o[mt][nt][2], c_o[mt][nt][3]);
        }
    __syncthreads();

    // epilogue: normalize + rel_v terms, write merged-head g_o
    const int bidx = bh >> 4, h = bh & 15;
    for (int idx = tid; idx < 128 * 16; idx += 256) {
        int r = idx >> 4, cc = (idx & 15) * 4;
        float linv = 1.f / l_row[r];
        float w0 = lo_row[r] * linv, w32 = hi_row[r] * linv;
        float4 acc = *(float4*)&sP[r * 68 + cc];
        acc.x *= linv; acc.y *= linv; acc.z *= linv; acc.w *= linv;
        const float* rv0 = rv + cc;
        const float* rv32 = rv + 32 * HDD + cc;
        acc.x += w0 * rv0[0] + w32 * rv32[0];
        acc.y += w0 * rv0[1] + w32 * rv32[1];
        acc.z += w0 * rv0[2] + w32 * rv32[2];
        acc.w += w0 * rv0[3] + w32 * rv32[3];
        for (int j = 0; j < 31; ++j) {
            float bw = band[r * 31 + j] * linv;
            const float* rj = rv + (j + 1) * HDD + cc;
            acc.x = fmaf(bw, rj[0], acc.x);
            acc.y = fmaf(bw, rj[1], acc.y);
            acc.z = fmaf(bw, rj[2], acc.z);
            acc.w = fmaf(bw, rj[3], acc.w);
        }
        *(float4*)&g_o[((size_t)bidx * LL + q0 + r) * DD + h * HDD + cc] = acc;
    }
}

// ---------------------------------------------------------------------------
extern "C" void kernel_launch(void* const* d_in, const int* in_sizes, int n_in,
                              void* d_out, int out_size) {
    const float* q     = (const float*)d_in[0];
    const float* k     = (const float*)d_in[1];
    const float* v     = (const float*)d_in[2];
    const float* Wq    = (const float*)d_in[3];
    const float* bq    = (const float*)d_in[4];
    const float* Wk    = (const float*)d_in[5];
    const float* bk    = (const float*)d_in[6];
    const float* Wv    = (const float*)d_in[7];
    const float* bv    = (const float*)d_in[8];
    const float* Wo    = (const float*)d_in[9];
    const float* bo    = (const float*)d_in[10];
    const float* rel_k = (const float*)d_in[11];
    const float* rel_v = (const float*)d_in[12];
    float* out = (float*)d_out;

    cudaFuncSetAttribute(proj_tc<0>, cudaFuncAttributeMaxDynamicSharedMemorySize, SMEM_BYTES);
    cudaFuncSetAttribute(proj_tc<1>, cudaFuncAttributeMaxDynamicSharedMemorySize, SMEM_BYTES);
    cudaFuncSetAttribute(proj_tc<2>, cudaFuncAttributeMaxDynamicSharedMemorySize, SMEM_BYTES);
    cudaFuncSetAttribute(proj_tc<3>, cudaFuncAttributeMaxDynamicSharedMemorySize, SMEM_BYTES);
    cudaFuncSetAttribute(flash_tc,   cudaFuncAttributeMaxDynamicSharedMemorySize, FLASH_SMEM);

    dim3 gproj(DD / 128, MLL / 128);                 // (8, 32)
    proj_tc<0><<<gproj, 256, SMEM_BYTES>>>(q, Wq, bq, nullptr);
    proj_tc<1><<<gproj, 256, SMEM_BYTES>>>(k, Wk, bk, nullptr);
    proj_tc<2><<<gproj, 256, SMEM_BYTES>>>(v, Wv, bv, nullptr);

    pcompute_kernel<<<BHH * LL / 8, dim3(33, 8)>>>(rel_k);

    flash_tc<<<dim3(LL / 128, BHH), 256, FLASH_SMEM>>>(rel_v);

    proj_tc<3><<<gproj, 256, SMEM_BYTES>>>(nullptr, Wo, bo, out);
}

// round 12
// speedup vs baseline: 3.1266x; 1.1053x over previous
#include <cuda_runtime.h>
#include <cstdint>
#include <math.h>

#define BB   2
#define NH   16
#define LL   2048
#define EE   1024
#define DD   1024
#define HDD  64
#define NDD  33
#define BHH  (BB*NH)
#define MLL  (BB*LL)
#define SCALE 0.03125f
#define LDA  36

// Scratch globals: 4 x 16 MiB = 64 MiB total (module-global footprint must stay
// well under ~128 MiB — lazy module load counts against the harness mem guard).
__device__ float g_qh[BHH * LL * HDD];
__device__ float g_kh[BHH * LL * HDD];
__device__ float g_vt[BHH * HDD * LL];    // transposed V: (bh, hd, l)
__device__ float g_o [MLL * DD];

#define SMEM_BYTES 73728

static __device__ __forceinline__ uint32_t tf32r(float x) {
    uint32_t y; asm("cvt.rna.tf32.f32 %0, %1;" : "=r"(y) : "f"(x)); return y;
}
static __device__ __forceinline__ float tf32f(float x) { return __uint_as_float(tf32r(x)); }
static __device__ __forceinline__ uint32_t f2u(float x) { return __float_as_uint(x); }

#define MMA8(c, a, b) \
    asm volatile("mma.sync.aligned.m16n8k8.row.col.f32.tf32.tf32.f32 " \
        "{%0,%1,%2,%3}, {%4,%5,%6,%7}, {%8,%9}, {%0,%1,%2,%3};" \
        : "+f"((c)[0]), "+f"((c)[1]), "+f"((c)[2]), "+f"((c)[3]) \
        : "r"((a)[0]), "r"((a)[1]), "r"((a)[2]), "r"((a)[3]), "r"((b)[0]), "r"((b)[1]))

static __device__ __forceinline__ void sts4(float* p, float4 v) {
    float4 o;
    o.x = tf32f(v.x); o.y = tf32f(v.y); o.z = tf32f(v.z); o.w = tf32f(v.w);
    *(float4*)p = o;
}

// ------------------- round-4 validated GEMM machinery ----------------------
template<int NTN>
static __device__ __forceinline__ void mma_tile(const float* sA, const float* sB,
    int wm, int wn, int g, int t4, float c[][NTN][4])
{
    #pragma unroll
    for (int ks = 0; ks < 4; ++ks) {
        const int kk = ks * 8;
        uint32_t a[4][4], b[NTN][2];
        #pragma unroll
        for (int mt = 0; mt < 4; ++mt) {
            const float* p = sA + (wm * 64 + mt * 16 + g) * LDA + kk + t4;
            a[mt][0] = f2u(p[0]); a[mt][1] = f2u(p[8 * LDA]);
            a[mt][2] = f2u(p[4]); a[mt][3] = f2u(p[8 * LDA + 4]);
        }
        #pragma unroll
        for (int nt = 0; nt < NTN; ++nt) {
            const float* p = sB + (wn * (NTN * 8) + nt * 8 + g) * LDA + kk + t4;
            b[nt][0] = f2u(p[0]); b[nt][1] = f2u(p[4]);
        }
        #pragma unroll
        for (int mt = 0; mt < 4; ++mt)
            #pragma unroll
            for (int nt = 0; nt < NTN; ++nt)
                MMA8(c[mt][nt], a[mt], b[nt]);
    }
}

// round-7 validated double-buffered mainloop (register prefetch + sts4 rounding)
template<int RB, int NTN, int BF4B>
static __device__ __forceinline__ void gemm_loop(const float* __restrict__ Ag, int lda,
    const float* __restrict__ Bg, int ldb, int NT, float* sm, float c[][NTN][4],
    int tid, int wm, int wn, int g, int t4)
{
    const int stageF = (128 + RB) * LDA;
    float* sA0 = sm;               float* sB0 = sm + 128 * LDA;
    float* sA1 = sm + stageF;      float* sB1 = sm + stageF + 128 * LDA;

    #pragma unroll
    for (int i = 0; i < 4; ++i) {
        int idx = tid + i * 256, r = idx >> 3, c4 = (idx & 7) * 4;
        sts4(sA0 + r * LDA + c4, *(const float4*)(Ag + (size_t)r * lda + c4));
    }
    #pragma unroll
    for (int i = 0; i < BF4B; ++i) {
        int idx = tid + i * 256, r = idx >> 3, c4 = (idx & 7) * 4;
        sts4(sB0 + r * LDA + c4, *(const float4*)(Bg + (size_t)r * ldb + c4));
    }
    __syncthreads();

    for (int t = 0; t < NT; ++t) {
        float* sA = (t & 1) ? sA1 : sA0;
        float* sB = (t & 1) ? sB1 : sB0;
        float4 pa[4], pb[BF4B];
        const bool more = (t + 1 < NT);
        if (more) {
            const int kt = (t + 1) * 32;
            #pragma unroll
            for (int i = 0; i < 4; ++i) {
                int idx = tid + i * 256, r = idx >> 3, c4 = (idx & 7) * 4;
                pa[i] = *(const float4*)(Ag + (size_t)r * lda + kt + c4);
            }
            #pragma unroll
            for (int i = 0; i < BF4B; ++i) {
                int idx = tid + i * 256, r = idx >> 3, c4 = (idx & 7) * 4;
                pb[i] = *(const float4*)(Bg + (size_t)r * ldb + kt + c4);
            }
        }
        mma_tile<NTN>(sA, sB, wm, wn, g, t4, c);
        if (more) {
            float* dA = (t & 1) ? sA0 : sA1;
            float* dB = (t & 1) ? sB0 : sB1;
            #pragma unroll
            for (int i = 0; i < 4; ++i) {
                int idx = tid + i * 256, r = idx >> 3, c4 = (idx & 7) * 4;
                sts4(dA + r * LDA + c4, pa[i]);
            }
            #pragma unroll
            for (int i = 0; i < BF4B; ++i) {
                int idx = tid + i * 256, r = idx >> 3, c4 = (idx & 7) * 4;
                sts4(dB + r * LDA + c4, pb[i]);
            }
        }
        __syncthreads();
    }
}

template<int NTN, int P>
static __device__ __forceinline__ void frag_to_epi(float* epi, float c[][NTN][4],
    int wm, int wn, int g, int t4)
{
    #pragma unroll
    for (int mt = 0; mt < 4; ++mt)
        #pragma unroll
        for (int nt = 0; nt < NTN; ++nt) {
            int r = wm * 64 + mt * 16 + g;
            int cc = wn * (NTN * 8) + nt * 8 + t4 * 2;
            *(float2*)&epi[r * P + cc]       = make_float2(c[mt][nt][0], c[mt][nt][1]);
            *(float2*)&epi[(r + 8) * P + cc] = make_float2(c[mt][nt][2], c[mt][nt][3]);
        }
}

// ---------------------------------------------------------------------------
// Projections: relu(A @ W^T + b). MODE 0->g_qh 1->g_kh 2->g_vt 3: g_o->outp
// MODE 0/1/2 outputs tf32-pre-rounded so flash_tc loads them raw.
// ---------------------------------------------------------------------------
template<int MODE>
__global__ void __launch_bounds__(256)
proj_tc(const float* __restrict__ A, const float* __restrict__ W,
        const float* __restrict__ bias, float* __restrict__ outp)
{
    extern __shared__ float sm[];
    const int tid = threadIdx.x, wid = tid >> 5, lane = tid & 31;
    const int wm = wid >> 2, wn = wid & 3, g = lane >> 2, t4 = lane & 3;
    const int n0 = blockIdx.x * 128, m0 = blockIdx.y * 128;
    const float* Ap = (MODE == 3) ? g_o : A;

    float c[4][4][4];
    #pragma unroll
    for (int i = 0; i < 4; ++i)
        #pragma unroll
        for (int j = 0; j < 4; ++j)
            #pragma unroll
            for (int e = 0; e < 4; ++e) c[i][j][e] = 0.f;

    gemm_loop<128, 4, 4>(Ap + (size_t)m0 * EE, EE, W + (size_t)n0 * EE, EE, 32,
                         sm, c, tid, wm, wn, g, t4);

    float* epi = sm;
    frag_to_epi<4, 132>(epi, c, wm, wn, g, t4);
    __syncthreads();

    const int bidx = m0 >> 11, l0 = m0 & (LL - 1);
    if (MODE == 2) {
        const int bh0 = bidx * NH + (n0 >> 6);
        for (int idx = tid; idx < 128 * 128; idx += 256) {
            int r = idx & 127, cc = idx >> 7;
            float v = tf32f(fmaxf(epi[r * 132 + cc] + __ldg(bias + n0 + cc), 0.f));
            g_vt[((size_t)(bh0 + (cc >> 6)) * HDD + (cc & 63)) * LL + l0 + r] = v;
        }
    } else {
        for (int idx = tid; idx < 128 * 32; idx += 256) {
            int r = idx >> 5, cc = (idx & 31) * 4;
            int n = n0 + cc;
            float4 v = *(float4*)&epi[r * 132 + cc];
            v.x = fmaxf(v.x + __ldg(bias + n),     0.f);
            v.y = fmaxf(v.y + __ldg(bias + n + 1), 0.f);
            v.z = fmaxf(v.z + __ldg(bias + n + 2), 0.f);
            v.w = fmaxf(v.w + __ldg(bias + n + 3), 0.f);
            if (MODE == 3) {
                *(float4*)(outp + (size_t)(m0 + r) * DD + n) = v;
            } else {
                v.x = tf32f(v.x); v.y = tf32f(v.y); v.z = tf32f(v.z); v.w = tf32f(v.w);
                float* dst = ((MODE == 0) ? g_qh : g_kh) +
                    (((size_t)(bidx * NH + (n >> 6))) * LL + l0 + r) * HDD + (n & 63);
                *(float4*)dst = v;
            }
        }
    }
}

// ---------------------------------------------------------------------------
// Fused flash attention + Shaw rel-pos. p computed inline (pcompute deleted);
// band stores RAW scores (no per-iteration rescale); tails as online sums.
// ---------------------------------------------------------------------------
#define F_SQ    0        // 128*68
#define F_SK    8704     // 64*68
#define F_SV    13056    // 64*68
#define F_SP    17408    // 128*68 (P; reused as epi staging)
#define F_PS    26112    // 128*36
#define F_BAND  30720    // 128*31 (raw scores)
#define F_RV    34688    // 33*64
#define F_RKT   36800    // 64*34
#define F_ALPHA 38976    // 128
#define F_LROW  39104    // 128
#define F_LO    39232    // 128
#define F_HI    39360    // 128
#define F_MROW  39488    // 128
#define FLASH_SMEM (39616 * 4)

__global__ void __launch_bounds__(256)
flash_tc(const float* __restrict__ rel_k, const float* __restrict__ rel_v)
{
    extern __shared__ float sm[];
    float* sQ   = sm + F_SQ;
    float* sK   = sm + F_SK;
    float* sV   = sm + F_SV;
    float* sP   = sm + F_SP;
    float* p_s  = sm + F_PS;
    float* band = sm + F_BAND;
    float* rv   = sm + F_RV;
    float* rkT  = sm + F_RKT;
    float* alpha_row = sm + F_ALPHA;
    float* l_row  = sm + F_LROW;
    float* lo_row = sm + F_LO;
    float* hi_row = sm + F_HI;
    float* m_row  = sm + F_MROW;

    const int tid = threadIdx.x, wid = tid >> 5, lane = tid & 31;
    const int g = lane >> 2, t4 = lane & 3;
    const int q0 = blockIdx.x * 128, bh = blockIdx.y;

    // one-time loads (g_qh pre-rounded by proj epilogue)
    const float* Qg = g_qh + ((size_t)bh * LL + q0) * HDD;
    #pragma unroll
    for (int i = 0; i < 8; ++i) {
        int idx = tid + i * 256, r = idx >> 4, c4 = (idx & 15) * 4;
        *(float4*)(sQ + r * 68 + c4) = *(const float4*)(Qg + (size_t)r * HDD + c4);
    }
    for (int idx = tid; idx < NDD * HDD; idx += 256) {
        rv[idx] = rel_v[idx];
        int j = idx >> 6, d = idx & 63;
        rkT[d * 34 + j] = rel_k[idx];
    }
    for (int idx = tid; idx < 128 * 31; idx += 256) band[idx] = -1e30f;
    __syncthreads();

    // inline p: p_s[r][j] = sQ[r] . rel_k[j]
    for (int idx = tid; idx < 128 * NDD; idx += 256) {
        int r = idx / 33, j = idx - r * 33;
        float s = 0.f;
        #pragma unroll
        for (int d = 0; d < HDD; ++d) s = fmaf(sQ[r * 68 + d], rkT[d * 34 + j], s);
        p_s[r * 36 + j] = s;
    }

    float m_r[2] = { -1e30f, -1e30f }, l_r[2] = { 0.f, 0.f };
    float lo_r[2] = { 0.f, 0.f }, hi_r[2] = { 0.f, 0.f };
    float c_o[4][2][4];
    #pragma unroll
    for (int mt = 0; mt < 4; ++mt)
        #pragma unroll
        for (int nt = 0; nt < 2; ++nt)
            #pragma unroll
            for (int e = 0; e < 4; ++e) c_o[mt][nt][e] = 0.f;

    const float* Kg = g_kh + (size_t)bh * LL * HDD;
    const float* Vg = g_vt + (size_t)bh * HDD * LL;

    for (int kt = 0; kt < 32; ++kt) {
        __syncthreads();
        #pragma unroll
        for (int i = 0; i < 4; ++i) {
            int idx = tid + i * 256, r = idx >> 4, c4 = (idx & 15) * 4;
            *(float4*)(sK + r * 68 + c4) = *(const float4*)(Kg + (size_t)(kt * 64 + r) * HDD + c4);
            *(float4*)(sV + r * 68 + c4) = *(const float4*)(Vg + (size_t)r * LL + kt * 64 + c4);
        }
        __syncthreads();

        // GEMM1: S(16q x 64k per warp)
        float cs[8][4];
        #pragma unroll
        for (int nt = 0; nt < 8; ++nt)
            #pragma unroll
            for (int e = 0; e < 4; ++e) cs[nt][e] = 0.f;
        #pragma unroll
        for (int ks = 0; ks < 8; ++ks) {
            int kk = ks * 8;
            const float* ap = sQ + (wid * 16 + g) * 68 + kk + t4;
            uint32_t a[4] = { f2u(ap[0]), f2u(ap[8 * 68]), f2u(ap[4]), f2u(ap[8 * 68 + 4]) };
            #pragma unroll
            for (int nt = 0; nt < 8; ++nt) {
                const float* bp = sK + (nt * 8 + g) * 68 + kk + t4;
                uint32_t b[2] = { f2u(bp[0]), f2u(bp[4]) };
                MMA8(cs[nt], a, b);
            }
        }

        // online softmax
        #pragma unroll
        for (int rr = 0; rr < 2; ++rr) {
            const int r = wid * 16 + g + rr * 8;
            const int qg = q0 + r;
            float sv[8][2], mx = -1e30f;
            #pragma unroll
            for (int nt = 0; nt < 8; ++nt)
                #pragma unroll
                for (int e = 0; e < 2; ++e) {
                    int kg = kt * 64 + nt * 8 + t4 * 2 + e;
                    int d = kg - qg;
                    int j = d < -16 ? -16 : (d > 16 ? 16 : d);
                    float v = (cs[nt][rr * 2 + e] + p_s[r * 36 + j + 16]) * SCALE;
                    sv[nt][e] = v;
                    mx = fmaxf(mx, v);
                }
            mx = fmaxf(mx, __shfl_xor_sync(0xffffffffu, mx, 1));
            mx = fmaxf(mx, __shfl_xor_sync(0xffffffffu, mx, 2));
            float mnew = fmaxf(m_r[rr], mx);
            float alpha = __expf(m_r[rr] - mnew);
            m_r[rr] = mnew;
            l_r[rr] *= alpha; lo_r[rr] *= alpha; hi_r[rr] *= alpha;
            if (t4 == 0) alpha_row[r] = alpha;
            float sum = 0.f, slo = 0.f, shi = 0.f;
            #pragma unroll
            for (int nt = 0; nt < 8; ++nt)
                #pragma unroll
                for (int e = 0; e < 2; ++e) {
                    int kg = kt * 64 + nt * 8 + t4 * 2 + e;
                    int d = kg - qg;
                    float p = __expf(sv[nt][e] - mnew);
                    sum += p;
                    if (d <= -16) slo += p;
                    else if (d >= 16) shi += p;
                    else band[r * 31 + d + 15] = sv[nt][e];   // raw score; no rescale
                    sP[r * 68 + nt * 8 + t4 * 2 + e] = tf32f(p);
                }
            sum += __shfl_xor_sync(0xffffffffu, sum, 1);
            sum += __shfl_xor_sync(0xffffffffu, sum, 2);
            slo += __shfl_xor_sync(0xffffffffu, slo, 1);
            slo += __shfl_xor_sync(0xffffffffu, slo, 2);
            shi += __shfl_xor_sync(0xffffffffu, shi, 1);
            shi += __shfl_xor_sync(0xffffffffu, shi, 2);
            l_r[rr] += sum; lo_r[rr] += slo; hi_r[rr] += shi;
        }
        __syncthreads();

        // rescale output accumulator
        #pragma unroll
        for (int mt = 0; mt < 4; ++mt) {
            int ro = (wid >> 2) * 64 + mt * 16 + g;
            float a0 = alpha_row[ro], a1 = alpha_row[ro + 8];
            #pragma unroll
            for (int nt = 0; nt < 2; ++nt) {
                c_o[mt][nt][0] *= a0; c_o[mt][nt][1] *= a0;
                c_o[mt][nt][2] *= a1; c_o[mt][nt][3] *= a1;
            }
        }

        // GEMM2: O += P @ V
        #pragma unroll
        for (int ks = 0; ks < 8; ++ks) {
            int kk = ks * 8;
            uint32_t b[2][2];
            #pragma unroll
            for (int nt = 0; nt < 2; ++nt) {
                const float* bp = sV + ((wid & 3) * 16 + nt * 8 + g) * 68 + kk + t4;
                b[nt][0] = f2u(bp[0]); b[nt][1] = f2u(bp[4]);
            }
            #pragma unroll
            for (int mt = 0; mt < 4; ++mt) {
                const float* ap = sP + ((wid >> 2) * 64 + mt * 16 + g) * 68 + kk + t4;
                uint32_t a[4] = { f2u(ap[0]), f2u(ap[8 * 68]), f2u(ap[4]), f2u(ap[8 * 68 + 4]) };
                #pragma unroll
                for (int nt = 0; nt < 2; ++nt) MMA8(c_o[mt][nt], a, b[nt]);
            }
        }
    }

    // publish per-row state
    #pragma unroll
    for (int rr = 0; rr < 2; ++rr) {
        int r = wid * 16 + g + rr * 8;
        if (t4 == 0) {
            l_row[r] = l_r[rr]; lo_row[r] = lo_r[rr];
            hi_row[r] = hi_r[rr]; m_row[r] = m_r[rr];
        }
    }
    __syncthreads();

    // stage c_o into sP
    #pragma unroll
    for (int mt = 0; mt < 4; ++mt)
        #pragma unroll
        for (int nt = 0; nt < 2; ++nt) {
            int r = (wid >> 2) * 64 + mt * 16 + g;
            int cc = (wid & 3) * 16 + nt * 8 + t4 * 2;
            *(float2*)&sP[r * 68 + cc]       = make_float2(c_o[mt][nt][0], c_o[mt][nt][1]);
            *(float2*)&sP[(r + 8) * 68 + cc] = make_float2(c_o[mt][nt][2], c_o[mt][nt][3]);
        }
    __syncthreads();

    // epilogue: normalize + rel_v terms, write merged-head g_o
    const int bidx = bh >> 4, h = bh & 15;
    for (int idx = tid; idx < 128 * 16; idx += 256) {
        int r = idx >> 4, cc = (idx & 15) * 4;
        float linv = 1.f / l_row[r];
        float mfin = m_row[r];
        float w0 = lo_row[r] * linv, w32 = hi_row[r] * linv;
        float4 acc = *(float4*)&sP[r * 68 + cc];
        acc.x *= linv; acc.y *= linv; acc.z *= linv; acc.w *= linv;
        const float* rv0 = rv + cc;
        const float* rv32 = rv + 32 * HDD + cc;
        acc.x += w0 * rv0[0] + w32 * rv32[0];
        acc.y += w0 * rv0[1] + w32 * rv32[1];
        acc.z += w0 * rv0[2] + w32 * rv32[2];
        acc.w += w0 * rv0[3] + w32 * rv32[3];
        for (int j = 0; j < 31; ++j) {
            float bw = __expf(band[r * 31 + j] - mfin) * linv;
            const float* rj = rv + (j + 1) * HDD + cc;
            acc.x = fmaf(bw, rj[0], acc.x);
            acc.y = fmaf(bw, rj[1], acc.y);
            acc.z = fmaf(bw, rj[2], acc.z);
            acc.w = fmaf(bw, rj[3], acc.w);
        }
        *(float4*)&g_o[((size_t)bidx * LL + q0 + r) * DD + h * HDD + cc] = acc;
    }
}

// ---------------------------------------------------------------------------
extern "C" void kernel_launch(void* const* d_in, const int* in_sizes, int n_in,
                              void* d_out, int out_size) {
    const float* q     = (const float*)d_in[0];
    const float* k     = (const float*)d_in[1];
    const float* v     = (const float*)d_in[2];
    const float* Wq    = (const float*)d_in[3];
    const float* bq    = (const float*)d_in[4];
    const float* Wk    = (const float*)d_in[5];
    const float* bk    = (const float*)d_in[6];
    const float* Wv    = (const float*)d_in[7];
    const float* bv    = (const float*)d_in[8];
    const float* Wo    = (const float*)d_in[9];
    const float* bo    = (const float*)d_in[10];
    const float* rel_k = (const float*)d_in[11];
    const float* rel_v = (const float*)d_in[12];
    float* out = (float*)d_out;

    cudaFuncSetAttribute(proj_tc<0>, cudaFuncAttributeMaxDynamicSharedMemorySize, SMEM_BYTES);
    cudaFuncSetAttribute(proj_tc<1>, cudaFuncAttributeMaxDynamicSharedMemorySize, SMEM_BYTES);
    cudaFuncSetAttribute(proj_tc<2>, cudaFuncAttributeMaxDynamicSharedMemorySize, SMEM_BYTES);
    cudaFuncSetAttribute(proj_tc<3>, cudaFuncAttributeMaxDynamicSharedMemorySize, SMEM_BYTES);
    cudaFuncSetAttribute(flash_tc,   cudaFuncAttributeMaxDynamicSharedMemorySize, FLASH_SMEM);

    dim3 gproj(DD / 128, MLL / 128);
    proj_tc<0><<<gproj, 256, SMEM_BYTES>>>(q, Wq, bq, nullptr);
    proj_tc<1><<<gproj, 256, SMEM_BYTES>>>(k, Wk, bk, nullptr);
    proj_tc<2><<<gproj, 256, SMEM_BYTES>>>(v, Wv, bv, nullptr);

    flash_tc<<<dim3(LL / 128, BHH), 256, FLASH_SMEM>>>(rel_k, rel_v);

    proj_tc<3><<<gproj, 256, SMEM_BYTES>>>(nullptr, Wo, bo, out);
}

// round 13
// speedup vs baseline: 3.1681x; 1.0133x over previous
#include <cuda_runtime.h>
#include <cstdint>
#include <math.h>

#define BB   2
#define NH   16
#define LL   2048
#define EE   1024
#define DD   1024
#define HDD  64
#define NDD  33
#define BHH  (BB*NH)
#define MLL  (BB*LL)
#define SCALE 0.03125f
#define LDA  36

// Scratch globals: 4 x 16 MiB = 64 MiB (module footprint must stay < ~76MB)
__device__ float g_qh[BHH * LL * HDD];
__device__ float g_kh[BHH * LL * HDD];
__device__ float g_vt[BHH * HDD * LL];    // transposed V: (bh, hd, l)
__device__ float g_o [MLL * DD];

#define SMEM_BYTES 73728

static __device__ __forceinline__ uint32_t tf32r(float x) {
    uint32_t y; asm("cvt.rna.tf32.f32 %0, %1;" : "=r"(y) : "f"(x)); return y;
}
static __device__ __forceinline__ float tf32f(float x) { return __uint_as_float(tf32r(x)); }
static __device__ __forceinline__ uint32_t f2u(float x) { return __float_as_uint(x); }
static __device__ __forceinline__ uint32_t s2u(const void* p) {
    uint32_t a;
    asm("{ .reg .u64 t; cvta.to.shared.u64 t, %1; cvt.u32.u64 %0, t; }" : "=r"(a) : "l"(p));
    return a;
}
#define CP16(dst, src) asm volatile("cp.async.cg.shared.global [%0], [%1], 16;" :: "r"(s2u(dst)), "l"(src))
#define CP_COMMIT()    asm volatile("cp.async.commit_group;" ::: "memory")
#define CP_WAIT0()     asm volatile("cp.async.wait_group 0;" ::: "memory")

#define MMA8(c, a, b) \
    asm volatile("mma.sync.aligned.m16n8k8.row.col.f32.tf32.tf32.f32 " \
        "{%0,%1,%2,%3}, {%4,%5,%6,%7}, {%8,%9}, {%0,%1,%2,%3};" \
        : "+f"((c)[0]), "+f"((c)[1]), "+f"((c)[2]), "+f"((c)[3]) \
        : "r"((a)[0]), "r"((a)[1]), "r"((a)[2]), "r"((a)[3]), "r"((b)[0]), "r"((b)[1]))

static __device__ __forceinline__ void sts4(float* p, float4 v) {
    float4 o;
    o.x = tf32f(v.x); o.y = tf32f(v.y); o.z = tf32f(v.z); o.w = tf32f(v.w);
    *(float4*)p = o;
}

// ------------------- round-4 validated GEMM machinery (projections) --------
template<int NTN>
static __device__ __forceinline__ void mma_tile(const float* sA, const float* sB,
    int wm, int wn, int g, int t4, float c[][NTN][4])
{
    #pragma unroll
    for (int ks = 0; ks < 4; ++ks) {
        const int kk = ks * 8;
        uint32_t a[4][4], b[NTN][2];
        #pragma unroll
        for (int mt = 0; mt < 4; ++mt) {
            const float* p = sA + (wm * 64 + mt * 16 + g) * LDA + kk + t4;
            a[mt][0] = f2u(p[0]); a[mt][1] = f2u(p[8 * LDA]);
            a[mt][2] = f2u(p[4]); a[mt][3] = f2u(p[8 * LDA + 4]);
        }
        #pragma unroll
        for (int nt = 0; nt < NTN; ++nt) {
            const float* p = sB + (wn * (NTN * 8) + nt * 8 + g) * LDA + kk + t4;
            b[nt][0] = f2u(p[0]); b[nt][1] = f2u(p[4]);
        }
        #pragma unroll
        for (int mt = 0; mt < 4; ++mt)
            #pragma unroll
            for (int nt = 0; nt < NTN; ++nt)
                MMA8(c[mt][nt], a[mt], b[nt]);
    }
}

template<int RB, int NTN, int BF4B>
static __device__ __forceinline__ void gemm_loop(const float* __restrict__ Ag, int lda,
    const float* __restrict__ Bg, int ldb, int NT, float* sm, float c[][NTN][4],
    int tid, int wm, int wn, int g, int t4)
{
    const int stageF = (128 + RB) * LDA;
    float* sA0 = sm;               float* sB0 = sm + 128 * LDA;
    float* sA1 = sm + stageF;      float* sB1 = sm + stageF + 128 * LDA;

    #pragma unroll
    for (int i = 0; i < 4; ++i) {
        int idx = tid + i * 256, r = idx >> 3, c4 = (idx & 7) * 4;
        sts4(sA0 + r * LDA + c4, *(const float4*)(Ag + (size_t)r * lda + c4));
    }
    #pragma unroll
    for (int i = 0; i < BF4B; ++i) {
        int idx = tid + i * 256, r = idx >> 3, c4 = (idx & 7) * 4;
        sts4(sB0 + r * LDA + c4, *(const float4*)(Bg + (size_t)r * ldb + c4));
    }
    __syncthreads();

    for (int t = 0; t < NT; ++t) {
        float* sA = (t & 1) ? sA1 : sA0;
        float* sB = (t & 1) ? sB1 : sB0;
        float4 pa[4], pb[BF4B];
        const bool more = (t + 1 < NT);
        if (more) {
            const int kt = (t + 1) * 32;
            #pragma unroll
            for (int i = 0; i < 4; ++i) {
                int idx = tid + i * 256, r = idx >> 3, c4 = (idx & 7) * 4;
                pa[i] = *(const float4*)(Ag + (size_t)r * lda + kt + c4);
            }
            #pragma unroll
            for (int i = 0; i < BF4B; ++i) {
                int idx = tid + i * 256, r = idx >> 3, c4 = (idx & 7) * 4;
                pb[i] = *(const float4*)(Bg + (size_t)r * ldb + kt + c4);
            }
        }
        mma_tile<NTN>(sA, sB, wm, wn, g, t4, c);
        if (more) {
            float* dA = (t & 1) ? sA0 : sA1;
            float* dB = (t & 1) ? sB0 : sB1;
            #pragma unroll
            for (int i = 0; i < 4; ++i) {
                int idx = tid + i * 256, r = idx >> 3, c4 = (idx & 7) * 4;
                sts4(dA + r * LDA + c4, pa[i]);
            }
            #pragma unroll
            for (int i = 0; i < BF4B; ++i) {
                int idx = tid + i * 256, r = idx >> 3, c4 = (idx & 7) * 4;
                sts4(dB + r * LDA + c4, pb[i]);
            }
        }
        __syncthreads();
    }
}

template<int NTN, int P>
static __device__ __forceinline__ void frag_to_epi(float* epi, float c[][NTN][4],
    int wm, int wn, int g, int t4)
{
    #pragma unroll
    for (int mt = 0; mt < 4; ++mt)
        #pragma unroll
        for (int nt = 0; nt < NTN; ++nt) {
            int r = wm * 64 + mt * 16 + g;
            int cc = wn * (NTN * 8) + nt * 8 + t4 * 2;
            *(float2*)&epi[r * P + cc]       = make_float2(c[mt][nt][0], c[mt][nt][1]);
            *(float2*)&epi[(r + 8) * P + cc] = make_float2(c[mt][nt][2], c[mt][nt][3]);
        }
}

// ---------------------------------------------------------------------------
// Projections: relu(A @ W^T + b). MODE 0->g_qh 1->g_kh 2->g_vt 3: g_o->outp
// ---------------------------------------------------------------------------
template<int MODE>
__global__ void __launch_bounds__(256)
proj_tc(const float* __restrict__ A, const float* __restrict__ W,
        const float* __restrict__ bias, float* __restrict__ outp)
{
    extern __shared__ float sm[];
    const int tid = threadIdx.x, wid = tid >> 5, lane = tid & 31;
    const int wm = wid >> 2, wn = wid & 3, g = lane >> 2, t4 = lane & 3;
    const int n0 = blockIdx.x * 128, m0 = blockIdx.y * 128;
    const float* Ap = (MODE == 3) ? g_o : A;

    float c[4][4][4];
    #pragma unroll
    for (int i = 0; i < 4; ++i)
        #pragma unroll
        for (int j = 0; j < 4; ++j)
            #pragma unroll
            for (int e = 0; e < 4; ++e) c[i][j][e] = 0.f;

    gemm_loop<128, 4, 4>(Ap + (size_t)m0 * EE, EE, W + (size_t)n0 * EE, EE, 32,
                         sm, c, tid, wm, wn, g, t4);

    float* epi = sm;
    frag_to_epi<4, 132>(epi, c, wm, wn, g, t4);
    __syncthreads();

    const int bidx = m0 >> 11, l0 = m0 & (LL - 1);
    if (MODE == 2) {
        const int bh0 = bidx * NH + (n0 >> 6);
        for (int idx = tid; idx < 128 * 128; idx += 256) {
            int r = idx & 127, cc = idx >> 7;
            float v = tf32f(fmaxf(epi[r * 132 + cc] + __ldg(bias + n0 + cc), 0.f));
            g_vt[((size_t)(bh0 + (cc >> 6)) * HDD + (cc & 63)) * LL + l0 + r] = v;
        }
    } else {
        for (int idx = tid; idx < 128 * 32; idx += 256) {
            int r = idx >> 5, cc = (idx & 31) * 4;
            int n = n0 + cc;
            float4 v = *(float4*)&epi[r * 132 + cc];
            v.x = fmaxf(v.x + __ldg(bias + n),     0.f);
            v.y = fmaxf(v.y + __ldg(bias + n + 1), 0.f);
            v.z = fmaxf(v.z + __ldg(bias + n + 2), 0.f);
            v.w = fmaxf(v.w + __ldg(bias + n + 3), 0.f);
            if (MODE == 3) {
                *(float4*)(outp + (size_t)(m0 + r) * DD + n) = v;
            } else {
                v.x = tf32f(v.x); v.y = tf32f(v.y); v.z = tf32f(v.z); v.w = tf32f(v.w);
                float* dst = ((MODE == 0) ? g_qh : g_kh) +
                    (((size_t)(bidx * NH + (n >> 6))) * LL + l0 + r) * HDD + (n & 63);
                *(float4*)dst = v;
            }
        }
    }
}

// ---------------------------------------------------------------------------
// Flash v2: warp-local GEMM2 (shfl P-repack), Q frags in regs, cp.async
// double-buffered K/V, ONE sync per k-tile. smem floats:
// ---------------------------------------------------------------------------
#define F_SK0   0        // 64*68
#define F_SV0   4352     // 64*68
#define F_SK1   8704     // 64*68  (aliases sQ during prologue)
#define F_SV1   13056    // 64*68
#define F_SQ    8704     // 128*68 prologue-only
#define F_PS    17408    // 128*36
#define F_BAND  22016    // 128*31 (raw scores)
#define F_RV    25984    // 33*64
#define F_RKT   28096    // 64*34
#define F_LROW  30272
#define F_LO    30400
#define F_HI    30528
#define F_MROW  30656
#define FLASH_SMEM (30784 * 4)

__global__ void __launch_bounds__(256)
flash_tc(const float* __restrict__ rel_k, const float* __restrict__ rel_v)
{
    extern __shared__ float sm[];
    float* p_s  = sm + F_PS;
    float* band = sm + F_BAND;
    float* rv   = sm + F_RV;
    float* rkT  = sm + F_RKT;
    float* l_row  = sm + F_LROW;
    float* lo_row = sm + F_LO;
    float* hi_row = sm + F_HI;
    float* m_row  = sm + F_MROW;

    const int tid = threadIdx.x, wid = tid >> 5, lane = tid & 31;
    const int g = lane >> 2, t4 = lane & 3;
    const int q0 = blockIdx.x * 128, bh = blockIdx.y;

    const float* Kg = g_kh + (size_t)bh * LL * HDD;
    const float* Vg = g_vt + (size_t)bh * HDD * LL;

    // issue KV tile 0 into buf0 (cp.async; doesn't touch sQ region)
    {
        int r = tid >> 4, c4 = (tid & 15) * 4;
        #pragma unroll
        for (int i = 0; i < 4; ++i) {
            int rr = r + i * 16;
            CP16(sm + F_SK0 + rr * 68 + c4, Kg + (size_t)rr * HDD + c4);
            CP16(sm + F_SV0 + rr * 68 + c4, Vg + (size_t)rr * LL + c4);
        }
        CP_COMMIT();
    }

    // prologue loads: sQ (aliases buf1), rkT, rv, band init
    float* sQ = sm + F_SQ;
    const float* Qg = g_qh + ((size_t)bh * LL + q0) * HDD;
    #pragma unroll
    for (int i = 0; i < 8; ++i) {
        int idx = tid + i * 256, r = idx >> 4, c4 = (idx & 15) * 4;
        *(float4*)(sQ + r * 68 + c4) = *(const float4*)(Qg + (size_t)r * HDD + c4);
    }
    for (int idx = tid; idx < NDD * HDD; idx += 256) {
        rv[idx] = rel_v[idx];
        int j = idx >> 6, d = idx & 63;
        rkT[d * 34 + j] = rel_k[idx];
    }
    for (int idx = tid; idx < 128 * 31; idx += 256) band[idx] = -1e30f;
    __syncthreads();

    // p_s[r][j] = sQ[r] . rel_k[j]
    for (int idx = tid; idx < 128 * NDD; idx += 256) {
        int r = idx / 33, j = idx - r * 33;
        float s = 0.f;
        #pragma unroll
        for (int d = 0; d < HDD; ++d) s = fmaf(sQ[r * 68 + d], rkT[d * 34 + j], s);
        p_s[r * 36 + j] = s;
    }

    // Q fragments (loop-invariant): rows wid*16+g / +8
    uint32_t qa[8][4];
    {
        const float* qp = sQ + (wid * 16 + g) * 68 + t4;
        #pragma unroll
        for (int ks = 0; ks < 8; ++ks) {
            qa[ks][0] = f2u(qp[ks * 8]);
            qa[ks][1] = f2u(qp[8 * 68 + ks * 8]);
            qa[ks][2] = f2u(qp[ks * 8 + 4]);
            qa[ks][3] = f2u(qp[8 * 68 + ks * 8 + 4]);
        }
    }
    CP_WAIT0();
    __syncthreads();   // buf0 ready; p_s/qa done; sQ region may now be overwritten

    float m_r[2] = { -1e30f, -1e30f }, l_r[2] = { 0.f, 0.f };
    float lo_r[2] = { 0.f, 0.f }, hi_r[2] = { 0.f, 0.f };
    float c_o[8][4];
    #pragma unroll
    for (int nt = 0; nt < 8; ++nt)
        #pragma unroll
        for (int e = 0; e < 4; ++e) c_o[nt][e] = 0.f;

    const int ldrow = tid >> 4, ldc4 = (tid & 15) * 4;

    for (int kt = 0; kt < 32; ++kt) {
        const int cur = kt & 1;
        const float* sK = sm + (cur ? F_SK1 : F_SK0);
        const float* sV = sm + (cur ? F_SV1 : F_SV0);
        // prefetch next KV into other buffer
        if (kt + 1 < 32) {
            float* dK = sm + (cur ? F_SK0 : F_SK1);
            float* dV = sm + (cur ? F_SV0 : F_SV1);
            #pragma unroll
            for (int i = 0; i < 4; ++i) {
                int rr = ldrow + i * 16;
                CP16(dK + rr * 68 + ldc4, Kg + (size_t)((kt + 1) * 64 + rr) * HDD + ldc4);
                CP16(dV + rr * 68 + ldc4, Vg + (size_t)rr * LL + (kt + 1) * 64 + ldc4);
            }
            CP_COMMIT();
        }

        // GEMM1: S(16q x 64k) per warp, Q from registers
        float cs[8][4];
        #pragma unroll
        for (int nt = 0; nt < 8; ++nt)
            #pragma unroll
            for (int e = 0; e < 4; ++e) cs[nt][e] = 0.f;
        #pragma unroll
        for (int ks = 0; ks < 8; ++ks) {
            const int kk = ks * 8;
            #pragma unroll
            for (int nt = 0; nt < 8; ++nt) {
                const float* bp = sK + (nt * 8 + g) * 68 + kk + t4;
                uint32_t b[2] = { f2u(bp[0]), f2u(bp[4]) };
                MMA8(cs[nt], qa[ks], b);
            }
        }

        // online softmax (fully warp-local); P written back into cs (tf32)
        float alpha01[2];
        #pragma unroll
        for (int rr = 0; rr < 2; ++rr) {
            const int r = wid * 16 + g + rr * 8;
            const int qg = q0 + r;
            float sv[8][2], mx = -1e30f;
            #pragma unroll
            for (int nt = 0; nt < 8; ++nt)
                #pragma unroll
                for (int e = 0; e < 2; ++e) {
                    int kg = kt * 64 + nt * 8 + t4 * 2 + e;
                    int d = kg - qg;
                    int j = d < -16 ? -16 : (d > 16 ? 16 : d);
                    float v = (cs[nt][rr * 2 + e] + p_s[r * 36 + j + 16]) * SCALE;
                    sv[nt][e] = v;
                    mx = fmaxf(mx, v);
                }
            mx = fmaxf(mx, __shfl_xor_sync(0xffffffffu, mx, 1));
            mx = fmaxf(mx, __shfl_xor_sync(0xffffffffu, mx, 2));
            float mnew = fmaxf(m_r[rr], mx);
            float alpha = __expf(m_r[rr] - mnew);
            m_r[rr] = mnew;
            alpha01[rr] = alpha;
            l_r[rr] *= alpha; lo_r[rr] *= alpha; hi_r[rr] *= alpha;
            float sum = 0.f, slo = 0.f, shi = 0.f;
            #pragma unroll
            for (int nt = 0; nt < 8; ++nt)
                #pragma unroll
                for (int e = 0; e < 2; ++e) {
                    int kg = kt * 64 + nt * 8 + t4 * 2 + e;
                    int d = kg - qg;
                    float p = __expf(sv[nt][e] - mnew);
                    sum += p;
                    if (d <= -16) slo += p;
                    else if (d >= 16) shi += p;
                    else band[r * 31 + d + 15] = sv[nt][e];   // raw score
                    cs[nt][rr * 2 + e] = tf32f(p);
                }
            sum += __shfl_xor_sync(0xffffffffu, sum, 1);
            sum += __shfl_xor_sync(0xffffffffu, sum, 2);
            slo += __shfl_xor_sync(0xffffffffu, slo, 1);
            slo += __shfl_xor_sync(0xffffffffu, slo, 2);
            shi += __shfl_xor_sync(0xffffffffu, shi, 1);
            shi += __shfl_xor_sync(0xffffffffu, shi, 2);
            l_r[rr] += sum; lo_r[rr] += slo; hi_r[rr] += shi;
        }

        // rescale output accumulator (warp-local alphas)
        #pragma unroll
        for (int nt = 0; nt < 8; ++nt) {
            c_o[nt][0] *= alpha01[0]; c_o[nt][1] *= alpha01[0];
            c_o[nt][2] *= alpha01[1]; c_o[nt][3] *= alpha01[1];
        }

        // GEMM2: O(16q x 64d) per warp; P repacked from cs via shuffles
        const int sl1 = (lane & ~3) | (t4 >> 1);
        const int sl2 = sl1 + 2;
        const bool odd = (t4 & 1);
        #pragma unroll
        for (int kc = 0; kc < 8; ++kc) {
            float x0 = __shfl_sync(0xffffffffu, cs[kc][0], sl1);
            float x1 = __shfl_sync(0xffffffffu, cs[kc][1], sl1);
            float x2 = __shfl_sync(0xffffffffu, cs[kc][2], sl1);
            float x3 = __shfl_sync(0xffffffffu, cs[kc][3], sl1);
            float y0 = __shfl_sync(0xffffffffu, cs[kc][0], sl2);
            float y1 = __shfl_sync(0xffffffffu, cs[kc][1], sl2);
            float y2 = __shfl_sync(0xffffffffu, cs[kc][2], sl2);
            float y3 = __shfl_sync(0xffffffffu, cs[kc][3], sl2);
            uint32_t a[4] = { f2u(odd ? x1 : x0), f2u(odd ? x3 : x2),
                              f2u(odd ? y1 : y0), f2u(odd ? y3 : y2) };
            const int kk = kc * 8;
            #pragma unroll
            for (int nd = 0; nd < 8; ++nd) {
                const float* bp = sV + (nd * 8 + g) * 68 + kk + t4;
                uint32_t b[2] = { f2u(bp[0]), f2u(bp[4]) };
                MMA8(c_o[nd], a, b);
            }
        }

        if (kt + 1 < 32) CP_WAIT0();
        __syncthreads();   // prefetched buffer visible; all reads of cur done
    }

    // publish per-row state
    #pragma unroll
    for (int rr = 0; rr < 2; ++rr) {
        int r = wid * 16 + g + rr * 8;
        if (t4 == 0) {
            l_row[r] = l_r[rr]; lo_row[r] = lo_r[rr];
            hi_row[r] = hi_r[rr]; m_row[r] = m_r[rr];
        }
    }

    // stage c_o into epi (aliases buf0; safe after final sync)
    float* epi = sm;
    {
        int r = wid * 16 + g;
        #pragma unroll
        for (int nd = 0; nd < 8; ++nd) {
            int cc = nd * 8 + t4 * 2;
            *(float2*)&epi[r * 68 + cc]       = make_float2(c_o[nd][0], c_o[nd][1]);
            *(float2*)&epi[(r + 8) * 68 + cc] = make_float2(c_o[nd][2], c_o[nd][3]);
        }
    }
    __syncthreads();

    // epilogue: normalize + rel_v terms, write merged-head g_o
    const int bidx = bh >> 4, h = bh & 15;
    for (int idx = tid; idx < 128 * 16; idx += 256) {
        int r = idx >> 4, cc = (idx & 15) * 4;
        float linv = 1.f / l_row[r];
        float mfin = m_row[r];
        float w0 = lo_row[r] * linv, w32 = hi_row[r] * linv;
        float4 acc = *(float4*)&epi[r * 68 + cc];
        acc.x *= linv; acc.y *= linv; acc.z *= linv; acc.w *= linv;
        const float* rv0 = rv + cc;
        const float* rv32 = rv + 32 * HDD + cc;
        acc.x += w0 * rv0[0] + w32 * rv32[0];
        acc.y += w0 * rv0[1] + w32 * rv32[1];
        acc.z += w0 * rv0[2] + w32 * rv32[2];
        acc.w += w0 * rv0[3] + w32 * rv32[3];
        for (int j = 0; j < 31; ++j) {
            float bw = __expf(band[r * 31 + j] - mfin) * linv;
            const float* rj = rv + (j + 1) * HDD + cc;
            acc.x = fmaf(bw, rj[0], acc.x);
            acc.y = fmaf(bw, rj[1], acc.y);
            acc.z = fmaf(bw, rj[2], acc.z);
            acc.w = fmaf(bw, rj[3], acc.w);
        }
        *(float4*)&g_o[((size_t)bidx * LL + q0 + r) * DD + h * HDD + cc] = acc;
    }
}

// ---------------------------------------------------------------------------
extern "C" void kernel_launch(void* const* d_in, const int* in_sizes, int n_in,
                              void* d_out, int out_size) {
    const float* q     = (const float*)d_in[0];
    const float* k     = (const float*)d_in[1];
    const float* v     = (const float*)d_in[2];
    const float* Wq    = (const float*)d_in[3];
    const float* bq    = (const float*)d_in[4];
    const float* Wk    = (const float*)d_in[5];
    const float* bk    = (const float*)d_in[6];
    const float* Wv    = (const float*)d_in[7];
    const float* bv    = (const float*)d_in[8];
    const float* Wo    = (const float*)d_in[9];
    const float* bo    = (const float*)d_in[10];
    const float* rel_k = (const float*)d_in[11];
    const float* rel_v = (const float*)d_in[12];
    float* out = (float*)d_out;

    cudaFuncSetAttribute(proj_tc<0>, cudaFuncAttributeMaxDynamicSharedMemorySize, SMEM_BYTES);
    cudaFuncSetAttribute(proj_tc<1>, cudaFuncAttributeMaxDynamicSharedMemorySize, SMEM_BYTES);
    cudaFuncSetAttribute(proj_tc<2>, cudaFuncAttributeMaxDynamicSharedMemorySize, SMEM_BYTES);
    cudaFuncSetAttribute(proj_tc<3>, cudaFuncAttributeMaxDynamicSharedMemorySize, SMEM_BYTES);
    cudaFuncSetAttribute(flash_tc,   cudaFuncAttributeMaxDynamicSharedMemorySize, FLASH_SMEM);

    dim3 gproj(DD / 128, MLL / 128);
    proj_tc<0><<<gproj, 256, SMEM_BYTES>>>(q, Wq, bq, nullptr);
    proj_tc<1><<<gproj, 256, SMEM_BYTES>>>(k, Wk, bk, nullptr);
    proj_tc<2><<<gproj, 256, SMEM_BYTES>>>(v, Wv, bv, nullptr);

    flash_tc<<<dim3(LL / 128, BHH), 256, FLASH_SMEM>>>(rel_k, rel_v);

    proj_tc<3><<<gproj, 256, SMEM_BYTES>>>(nullptr, Wo, bo, out);
}

// round 14
// speedup vs baseline: 3.3357x; 1.0529x over previous
#include <cuda_runtime.h>
#include <cstdint>
#include <math.h>

#define BB   2
#define NH   16
#define LL   2048
#define EE   1024
#define DD   1024
#define HDD  64
#define NDD  33
#define BHH  (BB*NH)
#define MLL  (BB*LL)
#define SCALE 0.03125f
#define LDA  36

// Scratch globals: 4 x 16 MiB = 64 MiB (module footprint must stay < ~76MB)
__device__ float g_qh[BHH * LL * HDD];
__device__ float g_kh[BHH * LL * HDD];
__device__ float g_vt[BHH * HDD * LL];    // transposed V: (bh, hd, l)
__device__ float g_o [MLL * DD];

#define SMEM_BYTES 73728

static __device__ __forceinline__ uint32_t tf32r(float x) {
    uint32_t y; asm("cvt.rna.tf32.f32 %0, %1;" : "=r"(y) : "f"(x)); return y;
}
static __device__ __forceinline__ float tf32f(float x) { return __uint_as_float(tf32r(x)); }
static __device__ __forceinline__ uint32_t f2u(float x) { return __float_as_uint(x); }
static __device__ __forceinline__ uint32_t s2u(const void* p) {
    uint32_t a;
    asm("{ .reg .u64 t; cvta.to.shared.u64 t, %1; cvt.u32.u64 %0, t; }" : "=r"(a) : "l"(p));
    return a;
}
#define CP16(dst, src) asm volatile("cp.async.cg.shared.global [%0], [%1], 16;" :: "r"(s2u(dst)), "l"(src))
#define CP_COMMIT()    asm volatile("cp.async.commit_group;" ::: "memory")
#define CP_WAIT0()     asm volatile("cp.async.wait_group 0;" ::: "memory")

#define MMA8(c, a, b) \
    asm volatile("mma.sync.aligned.m16n8k8.row.col.f32.tf32.tf32.f32 " \
        "{%0,%1,%2,%3}, {%4,%5,%6,%7}, {%8,%9}, {%0,%1,%2,%3};" \
        : "+f"((c)[0]), "+f"((c)[1]), "+f"((c)[2]), "+f"((c)[3]) \
        : "r"((a)[0]), "r"((a)[1]), "r"((a)[2]), "r"((a)[3]), "r"((b)[0]), "r"((b)[1]))

static __device__ __forceinline__ void sts4(float* p, float4 v) {
    float4 o;
    o.x = tf32f(v.x); o.y = tf32f(v.y); o.z = tf32f(v.z); o.w = tf32f(v.w);
    *(float4*)p = o;
}

// ------------------- round-4 validated GEMM machinery (projections) --------
template<int NTN>
static __device__ __forceinline__ void mma_tile(const float* sA, const float* sB,
    int wm, int wn, int g, int t4, float c[][NTN][4])
{
    #pragma unroll
    for (int ks = 0; ks < 4; ++ks) {
        const int kk = ks * 8;
        uint32_t a[4][4], b[NTN][2];
        #pragma unroll
        for (int mt = 0; mt < 4; ++mt) {
            const float* p = sA + (wm * 64 + mt * 16 + g) * LDA + kk + t4;
            a[mt][0] = f2u(p[0]); a[mt][1] = f2u(p[8 * LDA]);
            a[mt][2] = f2u(p[4]); a[mt][3] = f2u(p[8 * LDA + 4]);
        }
        #pragma unroll
        for (int nt = 0; nt < NTN; ++nt) {
            const float* p = sB + (wn * (NTN * 8) + nt * 8 + g) * LDA + kk + t4;
            b[nt][0] = f2u(p[0]); b[nt][1] = f2u(p[4]);
        }
        #pragma unroll
        for (int mt = 0; mt < 4; ++mt)
            #pragma unroll
            for (int nt = 0; nt < NTN; ++nt)
                MMA8(c[mt][nt], a[mt], b[nt]);
    }
}

template<int RB, int NTN, int BF4B>
static __device__ __forceinline__ void gemm_loop(const float* __restrict__ Ag, int lda,
    const float* __restrict__ Bg, int ldb, int NT, float* sm, float c[][NTN][4],
    int tid, int wm, int wn, int g, int t4)
{
    const int stageF = (128 + RB) * LDA;
    float* sA0 = sm;               float* sB0 = sm + 128 * LDA;
    float* sA1 = sm + stageF;      float* sB1 = sm + stageF + 128 * LDA;

    #pragma unroll
    for (int i = 0; i < 4; ++i) {
        int idx = tid + i * 256, r = idx >> 3, c4 = (idx & 7) * 4;
        sts4(sA0 + r * LDA + c4, *(const float4*)(Ag + (size_t)r * lda + c4));
    }
    #pragma unroll
    for (int i = 0; i < BF4B; ++i) {
        int idx = tid + i * 256, r = idx >> 3, c4 = (idx & 7) * 4;
        sts4(sB0 + r * LDA + c4, *(const float4*)(Bg + (size_t)r * ldb + c4));
    }
    __syncthreads();

    for (int t = 0; t < NT; ++t) {
        float* sA = (t & 1) ? sA1 : sA0;
        float* sB = (t & 1) ? sB1 : sB0;
        float4 pa[4], pb[BF4B];
        const bool more = (t + 1 < NT);
        if (more) {
            const int kt = (t + 1) * 32;
            #pragma unroll
            for (int i = 0; i < 4; ++i) {
                int idx = tid + i * 256, r = idx >> 3, c4 = (idx & 7) * 4;
                pa[i] = *(const float4*)(Ag + (size_t)r * lda + kt + c4);
            }
            #pragma unroll
            for (int i = 0; i < BF4B; ++i) {
                int idx = tid + i * 256, r = idx >> 3, c4 = (idx & 7) * 4;
                pb[i] = *(const float4*)(Bg + (size_t)r * ldb + kt + c4);
            }
        }
        mma_tile<NTN>(sA, sB, wm, wn, g, t4, c);
        if (more) {
            float* dA = (t & 1) ? sA0 : sA1;
            float* dB = (t & 1) ? sB0 : sB1;
            #pragma unroll
            for (int i = 0; i < 4; ++i) {
                int idx = tid + i * 256, r = idx >> 3, c4 = (idx & 7) * 4;
                sts4(dA + r * LDA + c4, pa[i]);
            }
            #pragma unroll
            for (int i = 0; i < BF4B; ++i) {
                int idx = tid + i * 256, r = idx >> 3, c4 = (idx & 7) * 4;
                sts4(dB + r * LDA + c4, pb[i]);
            }
        }
        __syncthreads();
    }
}

template<int NTN, int P>
static __device__ __forceinline__ void frag_to_epi(float* epi, float c[][NTN][4],
    int wm, int wn, int g, int t4)
{
    #pragma unroll
    for (int mt = 0; mt < 4; ++mt)
        #pragma unroll
        for (int nt = 0; nt < NTN; ++nt) {
            int r = wm * 64 + mt * 16 + g;
            int cc = wn * (NTN * 8) + nt * 8 + t4 * 2;
            *(float2*)&epi[r * P + cc]       = make_float2(c[mt][nt][0], c[mt][nt][1]);
            *(float2*)&epi[(r + 8) * P + cc] = make_float2(c[mt][nt][2], c[mt][nt][3]);
        }
}

// ---------------------------------------------------------------------------
// Projections: relu(A @ W^T + b). MODE 0->g_qh 1->g_kh 2->g_vt 3: g_o->outp
// ---------------------------------------------------------------------------
template<int MODE>
__global__ void __launch_bounds__(256)
proj_tc(const float* __restrict__ A, const float* __restrict__ W,
        const float* __restrict__ bias, float* __restrict__ outp)
{
    extern __shared__ float sm[];
    const int tid = threadIdx.x, wid = tid >> 5, lane = tid & 31;
    const int wm = wid >> 2, wn = wid & 3, g = lane >> 2, t4 = lane & 3;
    const int n0 = blockIdx.x * 128, m0 = blockIdx.y * 128;
    const float* Ap = (MODE == 3) ? g_o : A;

    float c[4][4][4];
    #pragma unroll
    for (int i = 0; i < 4; ++i)
        #pragma unroll
        for (int j = 0; j < 4; ++j)
            #pragma unroll
            for (int e = 0; e < 4; ++e) c[i][j][e] = 0.f;

    gemm_loop<128, 4, 4>(Ap + (size_t)m0 * EE, EE, W + (size_t)n0 * EE, EE, 32,
                         sm, c, tid, wm, wn, g, t4);

    float* epi = sm;
    frag_to_epi<4, 132>(epi, c, wm, wn, g, t4);
    __syncthreads();

    const int bidx = m0 >> 11, l0 = m0 & (LL - 1);
    if (MODE == 2) {
        const int bh0 = bidx * NH + (n0 >> 6);
        for (int idx = tid; idx < 128 * 128; idx += 256) {
            int r = idx & 127, cc = idx >> 7;
            float v = tf32f(fmaxf(epi[r * 132 + cc] + __ldg(bias + n0 + cc), 0.f));
            g_vt[((size_t)(bh0 + (cc >> 6)) * HDD + (cc & 63)) * LL + l0 + r] = v;
        }
    } else {
        for (int idx = tid; idx < 128 * 32; idx += 256) {
            int r = idx >> 5, cc = (idx & 31) * 4;
            int n = n0 + cc;
            float4 v = *(float4*)&epi[r * 132 + cc];
            v.x = fmaxf(v.x + __ldg(bias + n),     0.f);
            v.y = fmaxf(v.y + __ldg(bias + n + 1), 0.f);
            v.z = fmaxf(v.z + __ldg(bias + n + 2), 0.f);
            v.w = fmaxf(v.w + __ldg(bias + n + 3), 0.f);
            if (MODE == 3) {
                *(float4*)(outp + (size_t)(m0 + r) * DD + n) = v;
            } else {
                v.x = tf32f(v.x); v.y = tf32f(v.y); v.z = tf32f(v.z); v.w = tf32f(v.w);
                float* dst = ((MODE == 0) ? g_qh : g_kh) +
                    (((size_t)(bidx * NH + (n >> 6))) * LL + l0 + r) * HDD + (n & 63);
                *(float4*)dst = v;
            }
        }
    }
}

// ---------------------------------------------------------------------------
// Flash v3: 128 threads / 4 warps per CTA, q-tile 64 -> ~105KB smem
// -> 2 CTAs/SM (occupancy-bound fix). Warp-local GEMM2, shfl P-repack,
// Q frags in regs, cp.async double-buffered K/V, one sync per k-tile.
// smem (floats):
// ---------------------------------------------------------------------------
#define F_SK0   0        // 64*68
#define F_SV0   4352     // 64*68
#define F_SK1   8704     // 64*68 (aliases sQ during prologue)
#define F_SV1   13056    // 64*68
#define F_SQ    8704     // 64*68 prologue-only (aliases SK1)
#define F_PS    17408    // 64*36
#define F_BAND  19712    // 64*31 (raw scores)
#define F_RV    21696    // 33*64
#define F_RKT   23808    // 64*34
#define F_LROW  25984    // 64
#define F_LO    26048
#define F_HI    26112
#define F_MROW  26176
#define FLASH_SMEM (26240 * 4)   // 104,960 B -> 2 CTAs/SM

__global__ void __launch_bounds__(128)
flash_tc(const float* __restrict__ rel_k, const float* __restrict__ rel_v)
{
    extern __shared__ float sm[];
    float* p_s  = sm + F_PS;
    float* band = sm + F_BAND;
    float* rv   = sm + F_RV;
    float* rkT  = sm + F_RKT;
    float* l_row  = sm + F_LROW;
    float* lo_row = sm + F_LO;
    float* hi_row = sm + F_HI;
    float* m_row  = sm + F_MROW;

    const int tid = threadIdx.x, wid = tid >> 5, lane = tid & 31;
    const int g = lane >> 2, t4 = lane & 3;
    const int q0 = blockIdx.x * 64, bh = blockIdx.y;

    const float* Kg = g_kh + (size_t)bh * LL * HDD;
    const float* Vg = g_vt + (size_t)bh * HDD * LL;

    const int ldrow = tid >> 4, ldc4 = (tid & 15) * 4;  // 8 rows per pass

    // issue KV tile 0 into buf0 (cp.async; doesn't touch sQ region)
    #pragma unroll
    for (int i = 0; i < 8; ++i) {
        int rr = ldrow + i * 8;
        CP16(sm + F_SK0 + rr * 68 + ldc4, Kg + (size_t)rr * HDD + ldc4);
        CP16(sm + F_SV0 + rr * 68 + ldc4, Vg + (size_t)rr * LL + ldc4);
    }
    CP_COMMIT();

    // prologue: sQ (aliases buf1), rkT, rv, band init
    float* sQ = sm + F_SQ;
    const float* Qg = g_qh + ((size_t)bh * LL + q0) * HDD;
    #pragma unroll
    for (int i = 0; i < 8; ++i) {
        int rr = ldrow + i * 8;
        *(float4*)(sQ + rr * 68 + ldc4) = *(const float4*)(Qg + (size_t)rr * HDD + ldc4);
    }
    for (int idx = tid; idx < NDD * HDD; idx += 128) {
        rv[idx] = rel_v[idx];
        int j = idx >> 6, d = idx & 63;
        rkT[d * 34 + j] = rel_k[idx];
    }
    for (int idx = tid; idx < 64 * 31; idx += 128) band[idx] = -1e30f;
    __syncthreads();

    // p_s[r][j] = sQ[r] . rel_k[j]
    for (int idx = tid; idx < 64 * NDD; idx += 128) {
        int r = idx / 33, j = idx - r * 33;
        float s = 0.f;
        #pragma unroll
        for (int d = 0; d < HDD; ++d) s = fmaf(sQ[r * 68 + d], rkT[d * 34 + j], s);
        p_s[r * 36 + j] = s;
    }

    // Q fragments (loop-invariant): rows wid*16+g / +8
    uint32_t qa[8][4];
    {
        const float* qp = sQ + (wid * 16 + g) * 68 + t4;
        #pragma unroll
        for (int ks = 0; ks < 8; ++ks) {
            qa[ks][0] = f2u(qp[ks * 8]);
            qa[ks][1] = f2u(qp[8 * 68 + ks * 8]);
            qa[ks][2] = f2u(qp[ks * 8 + 4]);
            qa[ks][3] = f2u(qp[8 * 68 + ks * 8 + 4]);
        }
    }
    CP_WAIT0();
    __syncthreads();   // buf0 ready; p_s/qa done; sQ region may be overwritten

    float m_r[2] = { -1e30f, -1e30f }, l_r[2] = { 0.f, 0.f };
    float lo_r[2] = { 0.f, 0.f }, hi_r[2] = { 0.f, 0.f };
    float c_o[8][4];
    #pragma unroll
    for (int nt = 0; nt < 8; ++nt)
        #pragma unroll
        for (int e = 0; e < 4; ++e) c_o[nt][e] = 0.f;

    for (int kt = 0; kt < 32; ++kt) {
        const int cur = kt & 1;
        const float* sK = sm + (cur ? F_SK1 : F_SK0);
        const float* sV = sm + (cur ? F_SV1 : F_SV0);
        if (kt + 1 < 32) {
            float* dK = sm + (cur ? F_SK0 : F_SK1);
            float* dV = sm + (cur ? F_SV0 : F_SV1);
            #pragma unroll
            for (int i = 0; i < 8; ++i) {
                int rr = ldrow + i * 8;
                CP16(dK + rr * 68 + ldc4, Kg + (size_t)((kt + 1) * 64 + rr) * HDD + ldc4);
                CP16(dV + rr * 68 + ldc4, Vg + (size_t)rr * LL + (kt + 1) * 64 + ldc4);
            }
            CP_COMMIT();
        }

        // GEMM1: S(16q x 64k) per warp, Q from registers
        float cs[8][4];
        #pragma unroll
        for (int nt = 0; nt < 8; ++nt)
            #pragma unroll
            for (int e = 0; e < 4; ++e) cs[nt][e] = 0.f;
        #pragma unroll
        for (int ks = 0; ks < 8; ++ks) {
            const int kk = ks * 8;
            #pragma unroll
            for (int nt = 0; nt < 8; ++nt) {
                const float* bp = sK + (nt * 8 + g) * 68 + kk + t4;
                uint32_t b[2] = { f2u(bp[0]), f2u(bp[4]) };
                MMA8(cs[nt], qa[ks], b);
            }
        }

        // online softmax (warp-local); P written back into cs (tf32)
        float alpha01[2];
        #pragma unroll
        for (int rr = 0; rr < 2; ++rr) {
            const int r = wid * 16 + g + rr * 8;
            const int qg = q0 + r;
            float sv[8][2], mx = -1e30f;
            #pragma unroll
            for (int nt = 0; nt < 8; ++nt)
                #pragma unroll
                for (int e = 0; e < 2; ++e) {
                    int kg = kt * 64 + nt * 8 + t4 * 2 + e;
                    int d = kg - qg;
                    int j = d < -16 ? -16 : (d > 16 ? 16 : d);
                    float v = (cs[nt][rr * 2 + e] + p_s[r * 36 + j + 16]) * SCALE;
                    sv[nt][e] = v;
                    mx = fmaxf(mx, v);
                }
            mx = fmaxf(mx, __shfl_xor_sync(0xffffffffu, mx, 1));
            mx = fmaxf(mx, __shfl_xor_sync(0xffffffffu, mx, 2));
            float mnew = fmaxf(m_r[rr], mx);
            float alpha = __expf(m_r[rr] - mnew);
            m_r[rr] = mnew;
            alpha01[rr] = alpha;
            l_r[rr] *= alpha; lo_r[rr] *= alpha; hi_r[rr] *= alpha;
            float sum = 0.f, slo = 0.f, shi = 0.f;
            #pragma unroll
            for (int nt = 0; nt < 8; ++nt)
                #pragma unroll
                for (int e = 0; e < 2; ++e) {
                    int kg = kt * 64 + nt * 8 + t4 * 2 + e;
                    int d = kg - qg;
                    float p = __expf(sv[nt][e] - mnew);
                    sum += p;
                    if (d <= -16) slo += p;
                    else if (d >= 16) shi += p;
                    else band[r * 31 + d + 15] = sv[nt][e];   // raw score
                    cs[nt][rr * 2 + e] = tf32f(p);
                }
            sum += __shfl_xor_sync(0xffffffffu, sum, 1);
            sum += __shfl_xor_sync(0xffffffffu, sum, 2);
            slo += __shfl_xor_sync(0xffffffffu, slo, 1);
            slo += __shfl_xor_sync(0xffffffffu, slo, 2);
            shi += __shfl_xor_sync(0xffffffffu, shi, 1);
            shi += __shfl_xor_sync(0xffffffffu, shi, 2);
            l_r[rr] += sum; lo_r[rr] += slo; hi_r[rr] += shi;
        }

        // rescale output accumulator (warp-local alphas)
        #pragma unroll
        for (int nt = 0; nt < 8; ++nt) {
            c_o[nt][0] *= alpha01[0]; c_o[nt][1] *= alpha01[0];
            c_o[nt][2] *= alpha01[1]; c_o[nt][3] *= alpha01[1];
        }

        // GEMM2: O(16q x 64d) per warp; P repacked from cs via shuffles
        const int sl1 = (lane & ~3) | (t4 >> 1);
        const int sl2 = sl1 + 2;
        const bool odd = (t4 & 1);
        #pragma unroll
        for (int kc = 0; kc < 8; ++kc) {
            float x0 = __shfl_sync(0xffffffffu, cs[kc][0], sl1);
            float x1 = __shfl_sync(0xffffffffu, cs[kc][1], sl1);
            float x2 = __shfl_sync(0xffffffffu, cs[kc][2], sl1);
            float x3 = __shfl_sync(0xffffffffu, cs[kc][3], sl1);
            float y0 = __shfl_sync(0xffffffffu, cs[kc][0], sl2);
            float y1 = __shfl_sync(0xffffffffu, cs[kc][1], sl2);
            float y2 = __shfl_sync(0xffffffffu, cs[kc][2], sl2);
            float y3 = __shfl_sync(0xffffffffu, cs[kc][3], sl2);
            uint32_t a[4] = { f2u(odd ? x1 : x0), f2u(odd ? x3 : x2),
                              f2u(odd ? y1 : y0), f2u(odd ? y3 : y2) };
            const int kk = kc * 8;
            #pragma unroll
            for (int nd = 0; nd < 8; ++nd) {
                const float* bp = sV + (nd * 8 + g) * 68 + kk + t4;
                uint32_t b[2] = { f2u(bp[0]), f2u(bp[4]) };
                MMA8(c_o[nd], a, b);
            }
        }

        if (kt + 1 < 32) CP_WAIT0();
        __syncthreads();
    }

    // publish per-row state
    #pragma unroll
    for (int rr = 0; rr < 2; ++rr) {
        int r = wid * 16 + g + rr * 8;
        if (t4 == 0) {
            l_row[r] = l_r[rr]; lo_row[r] = lo_r[rr];
            hi_row[r] = hi_r[rr]; m_row[r] = m_r[rr];
        }
    }

    // stage c_o into epi (aliases buf0; safe after final sync)
    float* epi = sm;
    {
        int r = wid * 16 + g;
        #pragma unroll
        for (int nd = 0; nd < 8; ++nd) {
            int cc = nd * 8 + t4 * 2;
            *(float2*)&epi[r * 68 + cc]       = make_float2(c_o[nd][0], c_o[nd][1]);
            *(float2*)&epi[(r + 8) * 68 + cc] = make_float2(c_o[nd][2], c_o[nd][3]);
        }
    }
    __syncthreads();

    // epilogue: normalize + rel_v terms, write merged-head g_o
    const int bidx = bh >> 4, h = bh & 15;
    for (int idx = tid; idx < 64 * 16; idx += 128) {
        int r = idx >> 4, cc = (idx & 15) * 4;
        float linv = 1.f / l_row[r];
        float mfin = m_row[r];
        float w0 = lo_row[r] * linv, w32 = hi_row[r] * linv;
        float4 acc = *(float4*)&epi[r * 68 + cc];
        acc.x *= linv; acc.y *= linv; acc.z *= linv; acc.w *= linv;
        const float* rv0 = rv + cc;
        const float* rv32 = rv + 32 * HDD + cc;
        acc.x += w0 * rv0[0] + w32 * rv32[0];
        acc.y += w0 * rv0[1] + w32 * rv32[1];
        acc.z += w0 * rv0[2] + w32 * rv32[2];
        acc.w += w0 * rv0[3] + w32 * rv32[3];
        for (int j = 0; j < 31; ++j) {
            float bw = __expf(band[r * 31 + j] - mfin) * linv;
            const float* rj = rv + (j + 1) * HDD + cc;
            acc.x = fmaf(bw, rj[0], acc.x);
            acc.y = fmaf(bw, rj[1], acc.y);
            acc.z = fmaf(bw, rj[2], acc.z);
            acc.w = fmaf(bw, rj[3], acc.w);
        }
        *(float4*)&g_o[((size_t)bidx * LL + q0 + r) * DD + h * HDD + cc] = acc;
    }
}

// ---------------------------------------------------------------------------
extern "C" void kernel_launch(void* const* d_in, const int* in_sizes, int n_in,
                              void* d_out, int out_size) {
    const float* q     = (const float*)d_in[0];
    const float* k     = (const float*)d_in[1];
    const float* v     = (const float*)d_in[2];
    const float* Wq    = (const float*)d_in[3];
    const float* bq    = (const float*)d_in[4];
    const float* Wk    = (const float*)d_in[5];
    const float* bk    = (const float*)d_in[6];
    const float* Wv    = (const float*)d_in[7];
    const float* bv    = (const float*)d_in[8];
    const float* Wo    = (const float*)d_in[9];
    const float* bo    = (const float*)d_in[10];
    const float* rel_k = (const float*)d_in[11];
    const float* rel_v = (const float*)d_in[12];
    float* out = (float*)d_out;

    cudaFuncSetAttribute(proj_tc<0>, cudaFuncAttributeMaxDynamicSharedMemorySize, SMEM_BYTES);
    cudaFuncSetAttribute(proj_tc<1>, cudaFuncAttributeMaxDynamicSharedMemorySize, SMEM_BYTES);
    cudaFuncSetAttribute(proj_tc<2>, cudaFuncAttributeMaxDynamicSharedMemorySize, SMEM_BYTES);
    cudaFuncSetAttribute(proj_tc<3>, cudaFuncAttributeMaxDynamicSharedMemorySize, SMEM_BYTES);
    cudaFuncSetAttribute(flash_tc,   cudaFuncAttributeMaxDynamicSharedMemorySize, FLASH_SMEM);

    dim3 gproj(DD / 128, MLL / 128);
    proj_tc<0><<<gproj, 256, SMEM_BYTES>>>(q, Wq, bq, nullptr);
    proj_tc<1><<<gproj, 256, SMEM_BYTES>>>(k, Wk, bk, nullptr);
    proj_tc<2><<<gproj, 256, SMEM_BYTES>>>(v, Wv, bv, nullptr);

    flash_tc<<<dim3(LL / 64, BHH), 128, FLASH_SMEM>>>(rel_k, rel_v);

    proj_tc<3><<<gproj, 256, SMEM_BYTES>>>(nullptr, Wo, bo, out);
}

// round 15
// speedup vs baseline: 3.7100x; 1.1122x over previous
#include <cuda_runtime.h>
#include <cstdint>
#include <math.h>

#define BB   2
#define NH   16
#define LL   2048
#define EE   1024
#define DD   1024
#define HDD  64
#define NDD  33
#define BHH  (BB*NH)
#define MLL  (BB*LL)
#define SCALE 0.03125f
#define LDA  36

// Scratch globals: 4 x 16 MiB = 64 MiB (module footprint must stay < ~76MB)
__device__ float g_qh[BHH * LL * HDD];
__device__ float g_kh[BHH * LL * HDD];
__device__ float g_vt[BHH * HDD * LL];    // transposed V: (bh, hd, l)
__device__ float g_o [MLL * DD];

#define SMEM_BYTES 73728

static __device__ __forceinline__ uint32_t tf32r(float x) {
    uint32_t y; asm("cvt.rna.tf32.f32 %0, %1;" : "=r"(y) : "f"(x)); return y;
}
static __device__ __forceinline__ float tf32f(float x) { return __uint_as_float(tf32r(x)); }
static __device__ __forceinline__ uint32_t f2u(float x) { return __float_as_uint(x); }
static __device__ __forceinline__ uint32_t s2u(const void* p) {
    uint32_t a;
    asm("{ .reg .u64 t; cvta.to.shared.u64 t, %1; cvt.u32.u64 %0, t; }" : "=r"(a) : "l"(p));
    return a;
}
#define CP16(dst, src) asm volatile("cp.async.cg.shared.global [%0], [%1], 16;" :: "r"(s2u(dst)), "l"(src))
#define CP_COMMIT()    asm volatile("cp.async.commit_group;" ::: "memory")
#define CP_WAIT0()     asm volatile("cp.async.wait_group 0;" ::: "memory")

#define MMA8(c, a, b) \
    asm volatile("mma.sync.aligned.m16n8k8.row.col.f32.tf32.tf32.f32 " \
        "{%0,%1,%2,%3}, {%4,%5,%6,%7}, {%8,%9}, {%0,%1,%2,%3};" \
        : "+f"((c)[0]), "+f"((c)[1]), "+f"((c)[2]), "+f"((c)[3]) \
        : "r"((a)[0]), "r"((a)[1]), "r"((a)[2]), "r"((a)[3]), "r"((b)[0]), "r"((b)[1]))

static __device__ __forceinline__ void sts4(float* p, float4 v) {
    float4 o;
    o.x = tf32f(v.x); o.y = tf32f(v.y); o.z = tf32f(v.z); o.w = tf32f(v.w);
    *(float4*)p = o;
}

// ------------------- round-4 validated GEMM machinery (projections) --------
template<int NTN>
static __device__ __forceinline__ void mma_tile(const float* sA, const float* sB,
    int wm, int wn, int g, int t4, float c[][NTN][4])
{
    #pragma unroll
    for (int ks = 0; ks < 4; ++ks) {
        const int kk = ks * 8;
        uint32_t a[4][4], b[NTN][2];
        #pragma unroll
        for (int mt = 0; mt < 4; ++mt) {
            const float* p = sA + (wm * 64 + mt * 16 + g) * LDA + kk + t4;
            a[mt][0] = f2u(p[0]); a[mt][1] = f2u(p[8 * LDA]);
            a[mt][2] = f2u(p[4]); a[mt][3] = f2u(p[8 * LDA + 4]);
        }
        #pragma unroll
        for (int nt = 0; nt < NTN; ++nt) {
            const float* p = sB + (wn * (NTN * 8) + nt * 8 + g) * LDA + kk + t4;
            b[nt][0] = f2u(p[0]); b[nt][1] = f2u(p[4]);
        }
        #pragma unroll
        for (int mt = 0; mt < 4; ++mt)
            #pragma unroll
            for (int nt = 0; nt < NTN; ++nt)
                MMA8(c[mt][nt], a[mt], b[nt]);
    }
}

template<int RB, int NTN, int BF4B>
static __device__ __forceinline__ void gemm_loop(const float* __restrict__ Ag, int lda,
    const float* __restrict__ Bg, int ldb, int NT, float* sm, float c[][NTN][4],
    int tid, int wm, int wn, int g, int t4)
{
    const int stageF = (128 + RB) * LDA;
    float* sA0 = sm;               float* sB0 = sm + 128 * LDA;
    float* sA1 = sm + stageF;      float* sB1 = sm + stageF + 128 * LDA;

    #pragma unroll
    for (int i = 0; i < 4; ++i) {
        int idx = tid + i * 256, r = idx >> 3, c4 = (idx & 7) * 4;
        sts4(sA0 + r * LDA + c4, *(const float4*)(Ag + (size_t)r * lda + c4));
    }
    #pragma unroll
    for (int i = 0; i < BF4B; ++i) {
        int idx = tid + i * 256, r = idx >> 3, c4 = (idx & 7) * 4;
        sts4(sB0 + r * LDA + c4, *(const float4*)(Bg + (size_t)r * ldb + c4));
    }
    __syncthreads();

    for (int t = 0; t < NT; ++t) {
        float* sA = (t & 1) ? sA1 : sA0;
        float* sB = (t & 1) ? sB1 : sB0;
        float4 pa[4], pb[BF4B];
        const bool more = (t + 1 < NT);
        if (more) {
            const int kt = (t + 1) * 32;
            #pragma unroll
            for (int i = 0; i < 4; ++i) {
                int idx = tid + i * 256, r = idx >> 3, c4 = (idx & 7) * 4;
                pa[i] = *(const float4*)(Ag + (size_t)r * lda + kt + c4);
            }
            #pragma unroll
            for (int i = 0; i < BF4B; ++i) {
                int idx = tid + i * 256, r = idx >> 3, c4 = (idx & 7) * 4;
                pb[i] = *(const float4*)(Bg + (size_t)r * ldb + kt + c4);
            }
        }
        mma_tile<NTN>(sA, sB, wm, wn, g, t4, c);
        if (more) {
            float* dA = (t & 1) ? sA0 : sA1;
            float* dB = (t & 1) ? sB0 : sB1;
            #pragma unroll
            for (int i = 0; i < 4; ++i) {
                int idx = tid + i * 256, r = idx >> 3, c4 = (idx & 7) * 4;
                sts4(dA + r * LDA + c4, pa[i]);
            }
            #pragma unroll
            for (int i = 0; i < BF4B; ++i) {
                int idx = tid + i * 256, r = idx >> 3, c4 = (idx & 7) * 4;
                sts4(dB + r * LDA + c4, pb[i]);
            }
        }
        __syncthreads();
    }
}

template<int NTN, int P>
static __device__ __forceinline__ void frag_to_epi(float* epi, float c[][NTN][4],
    int wm, int wn, int g, int t4)
{
    #pragma unroll
    for (int mt = 0; mt < 4; ++mt)
        #pragma unroll
        for (int nt = 0; nt < NTN; ++nt) {
            int r = wm * 64 + mt * 16 + g;
            int cc = wn * (NTN * 8) + nt * 8 + t4 * 2;
            *(float2*)&epi[r * P + cc]       = make_float2(c[mt][nt][0], c[mt][nt][1]);
            *(float2*)&epi[(r + 8) * P + cc] = make_float2(c[mt][nt][2], c[mt][nt][3]);
        }
}

// ---------------------------------------------------------------------------
// Projections: relu(A @ W^T + b). MODE 0->g_qh 1->g_kh 2->g_vt 3: g_o->outp
// ---------------------------------------------------------------------------
template<int MODE>
__global__ void __launch_bounds__(256)
proj_tc(const float* __restrict__ A, const float* __restrict__ W,
        const float* __restrict__ bias, float* __restrict__ outp)
{
    extern __shared__ float sm[];
    const int tid = threadIdx.x, wid = tid >> 5, lane = tid & 31;
    const int wm = wid >> 2, wn = wid & 3, g = lane >> 2, t4 = lane & 3;
    const int n0 = blockIdx.x * 128, m0 = blockIdx.y * 128;
    const float* Ap = (MODE == 3) ? g_o : A;

    float c[4][4][4];
    #pragma unroll
    for (int i = 0; i < 4; ++i)
        #pragma unroll
        for (int j = 0; j < 4; ++j)
            #pragma unroll
            for (int e = 0; e < 4; ++e) c[i][j][e] = 0.f;

    gemm_loop<128, 4, 4>(Ap + (size_t)m0 * EE, EE, W + (size_t)n0 * EE, EE, 32,
                         sm, c, tid, wm, wn, g, t4);

    float* epi = sm;
    frag_to_epi<4, 132>(epi, c, wm, wn, g, t4);
    __syncthreads();

    const int bidx = m0 >> 11, l0 = m0 & (LL - 1);
    if (MODE == 2) {
        const int bh0 = bidx * NH + (n0 >> 6);
        for (int idx = tid; idx < 128 * 128; idx += 256) {
            int r = idx & 127, cc = idx >> 7;
            float v = tf32f(fmaxf(epi[r * 132 + cc] + __ldg(bias + n0 + cc), 0.f));
            g_vt[((size_t)(bh0 + (cc >> 6)) * HDD + (cc & 63)) * LL + l0 + r] = v;
        }
    } else {
        for (int idx = tid; idx < 128 * 32; idx += 256) {
            int r = idx >> 5, cc = (idx & 31) * 4;
            int n = n0 + cc;
            float4 v = *(float4*)&epi[r * 132 + cc];
            v.x = fmaxf(v.x + __ldg(bias + n),     0.f);
            v.y = fmaxf(v.y + __ldg(bias + n + 1), 0.f);
            v.z = fmaxf(v.z + __ldg(bias + n + 2), 0.f);
            v.w = fmaxf(v.w + __ldg(bias + n + 3), 0.f);
            if (MODE == 3) {
                *(float4*)(outp + (size_t)(m0 + r) * DD + n) = v;
            } else {
                v.x = tf32f(v.x); v.y = tf32f(v.y); v.z = tf32f(v.z); v.w = tf32f(v.w);
                float* dst = ((MODE == 0) ? g_qh : g_kh) +
                    (((size_t)(bidx * NH + (n >> 6))) * LL + l0 + r) * HDD + (n & 63);
                *(float4*)dst = v;
            }
        }
    }
}

// ---------------------------------------------------------------------------
// Flash v4: 128 threads, q-tile 64, K-tile 32, 64 iters, smem 71.2KB
// -> 3 CTAs/SM (regs 165*128*3 = 63360 < 64K). Warp-local GEMM2, shfl
// P-repack, Q frags in regs, cp.async double-buffered K/V, one sync/iter.
// smem (floats): K tile 32x68, V tile 64x36.
// ---------------------------------------------------------------------------
#define F_SK0   0        // 32*68 = 2176
#define F_SV0   2176     // 64*36 = 2304
#define F_SK1   4480     // 2176 (sQ aliases SK1+SV1 during prologue)
#define F_SV1   6656     // 2304
#define F_SQ    4480     // 64*68 = 4352 (prologue only)
#define F_PS    8960     // 64*36 = 2304
#define F_BAND  11264    // 64*31 = 1984 (raw scores)
#define F_RV    13248    // 33*64 = 2112
#define F_RKT   15360    // 64*34 = 2176
#define F_LROW  17536    // 64
#define F_LO    17600
#define F_HI    17664
#define F_MROW  17728
#define FLASH_SMEM (17792 * 4)   // 71,168 B

__global__ void __launch_bounds__(128)
flash_tc(const float* __restrict__ rel_k, const float* __restrict__ rel_v)
{
    extern __shared__ float sm[];
    float* p_s  = sm + F_PS;
    float* band = sm + F_BAND;
    float* rv   = sm + F_RV;
    float* rkT  = sm + F_RKT;
    float* l_row  = sm + F_LROW;
    float* lo_row = sm + F_LO;
    float* hi_row = sm + F_HI;
    float* m_row  = sm + F_MROW;

    const int tid = threadIdx.x, wid = tid >> 5, lane = tid & 31;
    const int g = lane >> 2, t4 = lane & 3;
    const int q0 = blockIdx.x * 64, bh = blockIdx.y;

    const float* Kg = g_kh + (size_t)bh * LL * HDD;
    const float* Vg = g_vt + (size_t)bh * HDD * LL;

    // K loader map: 8 rows x 64 cols per pass; V loader: 16 rows x 32 cols per pass
    const int krow = tid >> 4, kc4 = (tid & 15) * 4;
    const int vrow = tid >> 3, vc4 = (tid & 7) * 4;

    // KV tile 0 -> buf0 (doesn't touch sQ region)
    #pragma unroll
    for (int i = 0; i < 4; ++i) {
        int rr = krow + i * 8;
        CP16(sm + F_SK0 + rr * 68 + kc4, Kg + (size_t)rr * HDD + kc4);
        int vr = vrow + i * 16;
        CP16(sm + F_SV0 + vr * 36 + vc4, Vg + (size_t)vr * LL + vc4);
    }
    CP_COMMIT();

    // prologue: sQ (aliases buf1), rkT, rv, band init
    float* sQ = sm + F_SQ;
    const float* Qg = g_qh + ((size_t)bh * LL + q0) * HDD;
    #pragma unroll
    for (int i = 0; i < 8; ++i) {
        int rr = krow + i * 8;
        *(float4*)(sQ + rr * 68 + kc4) = *(const float4*)(Qg + (size_t)rr * HDD + kc4);
    }
    for (int idx = tid; idx < NDD * HDD; idx += 128) {
        rv[idx] = rel_v[idx];
        int j = idx >> 6, d = idx & 63;
        rkT[d * 34 + j] = rel_k[idx];
    }
    for (int idx = tid; idx < 64 * 31; idx += 128) band[idx] = -1e30f;
    __syncthreads();

    // p_s[r][j] = sQ[r] . rel_k[j]
    for (int idx = tid; idx < 64 * NDD; idx += 128) {
        int r = idx / 33, j = idx - r * 33;
        float s = 0.f;
        #pragma unroll
        for (int d = 0; d < HDD; ++d) s = fmaf(sQ[r * 68 + d], rkT[d * 34 + j], s);
        p_s[r * 36 + j] = s;
    }

    // Q fragments (loop-invariant): rows wid*16+g / +8
    uint32_t qa[8][4];
    {
        const float* qp = sQ + (wid * 16 + g) * 68 + t4;
        #pragma unroll
        for (int ks = 0; ks < 8; ++ks) {
            qa[ks][0] = f2u(qp[ks * 8]);
            qa[ks][1] = f2u(qp[8 * 68 + ks * 8]);
            qa[ks][2] = f2u(qp[ks * 8 + 4]);
            qa[ks][3] = f2u(qp[8 * 68 + ks * 8 + 4]);
        }
    }
    CP_WAIT0();
    __syncthreads();   // buf0 ready; p_s/qa done; sQ region may be overwritten

    float m_r[2] = { -1e30f, -1e30f }, l_r[2] = { 0.f, 0.f };
    float lo_r[2] = { 0.f, 0.f }, hi_r[2] = { 0.f, 0.f };
    float c_o[8][4];
    #pragma unroll
    for (int nt = 0; nt < 8; ++nt)
        #pragma unroll
        for (int e = 0; e < 4; ++e) c_o[nt][e] = 0.f;

    for (int kt = 0; kt < 64; ++kt) {
        const int cur = kt & 1;
        const float* sK = sm + (cur ? F_SK1 : F_SK0);
        const float* sV = sm + (cur ? F_SV1 : F_SV0);
        if (kt + 1 < 64) {
            float* dK = sm + (cur ? F_SK0 : F_SK1);
            float* dV = sm + (cur ? F_SV0 : F_SV1);
            #pragma unroll
            for (int i = 0; i < 2; ++i) {
                int rr = krow + i * 8;       // wait: 32 rows need 4 passes of 8
                CP16(dK + rr * 68 + kc4, Kg + (size_t)((kt + 1) * 32 + rr) * HDD + kc4);
                CP16(dK + (rr + 16) * 68 + kc4, Kg + (size_t)((kt + 1) * 32 + rr + 16) * HDD + kc4);
                int vr = vrow + i * 16;      // 64 rows need 4 passes of 16
                CP16(dV + vr * 36 + vc4, Vg + (size_t)vr * LL + (kt + 1) * 32 + vc4);
                CP16(dV + (vr + 32) * 36 + vc4, Vg + (size_t)(vr + 32) * LL + (kt + 1) * 32 + vc4);
            }
            CP_COMMIT();
        }

        // GEMM1: S(16q x 32k) per warp, Q from registers
        float cs[4][4];
        #pragma unroll
        for (int nt = 0; nt < 4; ++nt)
            #pragma unroll
            for (int e = 0; e < 4; ++e) cs[nt][e] = 0.f;
        #pragma unroll
        for (int ks = 0; ks < 8; ++ks) {
            const int kk = ks * 8;
            #pragma unroll
            for (int nt = 0; nt < 4; ++nt) {
                const float* bp = sK + (nt * 8 + g) * 68 + kk + t4;
                uint32_t b[2] = { f2u(bp[0]), f2u(bp[4]) };
                MMA8(cs[nt], qa[ks], b);
            }
        }

        // online softmax (warp-local); P written back into cs (tf32)
        float alpha01[2];
        #pragma unroll
        for (int rr = 0; rr < 2; ++rr) {
            const int r = wid * 16 + g + rr * 8;
            const int qg = q0 + r;
            float sv[4][2], mx = -1e30f;
            #pragma unroll
            for (int nt = 0; nt < 4; ++nt)
                #pragma unroll
                for (int e = 0; e < 2; ++e) {
                    int kg = kt * 32 + nt * 8 + t4 * 2 + e;
                    int d = kg - qg;
                    int j = d < -16 ? -16 : (d > 16 ? 16 : d);
                    float v = (cs[nt][rr * 2 + e] + p_s[r * 36 + j + 16]) * SCALE;
                    sv[nt][e] = v;
                    mx = fmaxf(mx, v);
                }
            mx = fmaxf(mx, __shfl_xor_sync(0xffffffffu, mx, 1));
            mx = fmaxf(mx, __shfl_xor_sync(0xffffffffu, mx, 2));
            float mnew = fmaxf(m_r[rr], mx);
            float alpha = __expf(m_r[rr] - mnew);
            m_r[rr] = mnew;
            alpha01[rr] = alpha;
            l_r[rr] *= alpha; lo_r[rr] *= alpha; hi_r[rr] *= alpha;
            float sum = 0.f, slo = 0.f, shi = 0.f;
            #pragma unroll
            for (int nt = 0; nt < 4; ++nt)
                #pragma unroll
                for (int e = 0; e < 2; ++e) {
                    int kg = kt * 32 + nt * 8 + t4 * 2 + e;
                    int d = kg - qg;
                    float p = __expf(sv[nt][e] - mnew);
                    sum += p;
                    if (d <= -16) slo += p;
                    else if (d >= 16) shi += p;
                    else band[r * 31 + d + 15] = sv[nt][e];   // raw score
                    cs[nt][rr * 2 + e] = tf32f(p);
                }
            sum += __shfl_xor_sync(0xffffffffu, sum, 1);
            sum += __shfl_xor_sync(0xffffffffu, sum, 2);
            slo += __shfl_xor_sync(0xffffffffu, slo, 1);
            slo += __shfl_xor_sync(0xffffffffu, slo, 2);
            shi += __shfl_xor_sync(0xffffffffu, shi, 1);
            shi += __shfl_xor_sync(0xffffffffu, shi, 2);
            l_r[rr] += sum; lo_r[rr] += slo; hi_r[rr] += shi;
        }

        // rescale output accumulator (warp-local alphas)
        #pragma unroll
        for (int nt = 0; nt < 8; ++nt) {
            c_o[nt][0] *= alpha01[0]; c_o[nt][1] *= alpha01[0];
            c_o[nt][2] *= alpha01[1]; c_o[nt][3] *= alpha01[1];
        }

        // GEMM2: O(16q x 64d) per warp; P repacked from cs via shuffles
        const int sl1 = (lane & ~3) | (t4 >> 1);
        const int sl2 = sl1 + 2;
        const bool odd = (t4 & 1);
        #pragma unroll
        for (int kc = 0; kc < 4; ++kc) {
            float x0 = __shfl_sync(0xffffffffu, cs[kc][0], sl1);
            float x1 = __shfl_sync(0xffffffffu, cs[kc][1], sl1);
            float x2 = __shfl_sync(0xffffffffu, cs[kc][2], sl1);
            float x3 = __shfl_sync(0xffffffffu, cs[kc][3], sl1);
            float y0 = __shfl_sync(0xffffffffu, cs[kc][0], sl2);
            float y1 = __shfl_sync(0xffffffffu, cs[kc][1], sl2);
            float y2 = __shfl_sync(0xffffffffu, cs[kc][2], sl2);
            float y3 = __shfl_sync(0xffffffffu, cs[kc][3], sl2);
            uint32_t a[4] = { f2u(odd ? x1 : x0), f2u(odd ? x3 : x2),
                              f2u(odd ? y1 : y0), f2u(odd ? y3 : y2) };
            const int kk = kc * 8;
            #pragma unroll
            for (int nd = 0; nd < 8; ++nd) {
                const float* bp = sV + (nd * 8 + g) * 36 + kk + t4;
                uint32_t b[2] = { f2u(bp[0]), f2u(bp[4]) };
                MMA8(c_o[nd], a, b);
            }
        }

        if (kt + 1 < 64) CP_WAIT0();
        __syncthreads();
    }

    // publish per-row state
    #pragma unroll
    for (int rr = 0; rr < 2; ++rr) {
        int r = wid * 16 + g + rr * 8;
        if (t4 == 0) {
            l_row[r] = l_r[rr]; lo_row[r] = lo_r[rr];
            hi_row[r] = hi_r[rr]; m_row[r] = m_r[rr];
        }
    }

    // stage c_o into epi (aliases buf0 region; pitch 68; safe after final sync)
    float* epi = sm;
    {
        int r = wid * 16 + g;
        #pragma unroll
        for (int nd = 0; nd < 8; ++nd) {
            int cc = nd * 8 + t4 * 2;
            *(float2*)&epi[r * 68 + cc]       = make_float2(c_o[nd][0], c_o[nd][1]);
            *(float2*)&epi[(r + 8) * 68 + cc] = make_float2(c_o[nd][2], c_o[nd][3]);
        }
    }
    __syncthreads();

    // epilogue: normalize + rel_v terms, write merged-head g_o
    const int bidx = bh >> 4, h = bh & 15;
    for (int idx = tid; idx < 64 * 16; idx += 128) {
        int r = idx >> 4, cc = (idx & 15) * 4;
        float linv = 1.f / l_row[r];
        float mfin = m_row[r];
        float w0 = lo_row[r] * linv, w32 = hi_row[r] * linv;
        float4 acc = *(float4*)&epi[r * 68 + cc];
        acc.x *= linv; acc.y *= linv; acc.z *= linv; acc.w *= linv;
        const float* rv0 = rv + cc;
        const float* rv32 = rv + 32 * HDD + cc;
        acc.x += w0 * rv0[0] + w32 * rv32[0];
        acc.y += w0 * rv0[1] + w32 * rv32[1];
        acc.z += w0 * rv0[2] + w32 * rv32[2];
        acc.w += w0 * rv0[3] + w32 * rv32[3];
        for (int j = 0; j < 31; ++j) {
            float bw = __expf(band[r * 31 + j] - mfin) * linv;
            const float* rj = rv + (j + 1) * HDD + cc;
            acc.x = fmaf(bw, rj[0], acc.x);
            acc.y = fmaf(bw, rj[1], acc.y);
            acc.z = fmaf(bw, rj[2], acc.z);
            acc.w = fmaf(bw, rj[3], acc.w);
        }
        *(float4*)&g_o[((size_t)bidx * LL + q0 + r) * DD + h * HDD + cc] = acc;
    }
}

// ---------------------------------------------------------------------------
extern "C" void kernel_launch(void* const* d_in, const int* in_sizes, int n_in,
                              void* d_out, int out_size) {
    const float* q     = (const float*)d_in[0];
    const float* k     = (const float*)d_in[1];
    const float* v     = (const float*)d_in[2];
    const float* Wq    = (const float*)d_in[3];
    const float* bq    = (const float*)d_in[4];
    const float* Wk    = (const float*)d_in[5];
    const float* bk    = (const float*)d_in[6];
    const float* Wv    = (const float*)d_in[7];
    const float* bv    = (const float*)d_in[8];
    const float* Wo    = (const float*)d_in[9];
    const float* bo    = (const float*)d_in[10];
    const float* rel_k = (const float*)d_in[11];
    const float* rel_v = (const float*)d_in[12];
    float* out = (float*)d_out;

    cudaFuncSetAttribute(proj_tc<0>, cudaFuncAttributeMaxDynamicSharedMemorySize, SMEM_BYTES);
    cudaFuncSetAttribute(proj_tc<1>, cudaFuncAttributeMaxDynamicSharedMemorySize, SMEM_BYTES);
    cudaFuncSetAttribute(proj_tc<2>, cudaFuncAttributeMaxDynamicSharedMemorySize, SMEM_BYTES);
    cudaFuncSetAttribute(proj_tc<3>, cudaFuncAttributeMaxDynamicSharedMemorySize, SMEM_BYTES);
    cudaFuncSetAttribute(flash_tc,   cudaFuncAttributeMaxDynamicSharedMemorySize, FLASH_SMEM);

    dim3 gproj(DD / 128, MLL / 128);
    proj_tc<0><<<gproj, 256, SMEM_BYTES>>>(q, Wq, bq, nullptr);
    proj_tc<1><<<gproj, 256, SMEM_BYTES>>>(k, Wk, bk, nullptr);
    proj_tc<2><<<gproj, 256, SMEM_BYTES>>>(v, Wv, bv, nullptr);

    flash_tc<<<dim3(LL / 64, BHH), 128, FLASH_SMEM>>>(rel_k, rel_v);

    proj_tc<3><<<gproj, 256, SMEM_BYTES>>>(nullptr, Wo, bo, out);
}

// round 17
// speedup vs baseline: 4.0119x; 1.0814x over previous
#include <cuda_runtime.h>
#include <cstdint>
#include <math.h>

#define BB   2
#define NH   16
#define LL   2048
#define EE   1024
#define DD   1024
#define HDD  64
#define NDD  33
#define BHH  (BB*NH)
#define MLL  (BB*LL)
#define SCALE 0.03125f
#define LDA  36

// Scratch globals: 4 x 16 MiB = 64 MiB (module footprint must stay < ~76MB)
__device__ float g_qh[BHH * LL * HDD];
__device__ float g_kh[BHH * LL * HDD];
__device__ float g_vt[BHH * HDD * LL];    // transposed V: (bh, hd, l)
__device__ float g_o [MLL * DD];

#define SMEM_BYTES 73728

static __device__ __forceinline__ uint32_t tf32r(float x) {
    uint32_t y; asm("cvt.rna.tf32.f32 %0, %1;" : "=r"(y) : "f"(x)); return y;
}
static __device__ __forceinline__ float tf32f(float x) { return __uint_as_float(tf32r(x)); }
static __device__ __forceinline__ uint32_t f2u(float x) { return __float_as_uint(x); }
static __device__ __forceinline__ uint32_t s2u(const void* p) {
    uint32_t a;
    asm("{ .reg .u64 t; cvta.to.shared.u64 t, %1; cvt.u32.u64 %0, t; }" : "=r"(a) : "l"(p));
    return a;
}
#define CP16(dst, src) asm volatile("cp.async.cg.shared.global [%0], [%1], 16;" :: "r"(s2u(dst)), "l"(src))
#define CP_COMMIT()    asm volatile("cp.async.commit_group;" ::: "memory")
#define CP_WAIT0()     asm volatile("cp.async.wait_group 0;" ::: "memory")

#define MMA8(c, a, b) \
    asm volatile("mma.sync.aligned.m16n8k8.row.col.f32.tf32.tf32.f32 " \
        "{%0,%1,%2,%3}, {%4,%5,%6,%7}, {%8,%9}, {%0,%1,%2,%3};" \
        : "+f"((c)[0]), "+f"((c)[1]), "+f"((c)[2]), "+f"((c)[3]) \
        : "r"((a)[0]), "r"((a)[1]), "r"((a)[2]), "r"((a)[3]), "r"((b)[0]), "r"((b)[1]))

static __device__ __forceinline__ void sts4(float* p, float4 v) {
    float4 o;
    o.x = tf32f(v.x); o.y = tf32f(v.y); o.z = tf32f(v.z); o.w = tf32f(v.w);
    *(float4*)p = o;
}

// ------------------- round-4 validated GEMM machinery (projections) --------
template<int NTN>
static __device__ __forceinline__ void mma_tile(const float* sA, const float* sB,
    int wm, int wn, int g, int t4, float c[][NTN][4])
{
    #pragma unroll
    for (int ks = 0; ks < 4; ++ks) {
        const int kk = ks * 8;
        uint32_t a[4][4], b[NTN][2];
        #pragma unroll
        for (int mt = 0; mt < 4; ++mt) {
            const float* p = sA + (wm * 64 + mt * 16 + g) * LDA + kk + t4;
            a[mt][0] = f2u(p[0]); a[mt][1] = f2u(p[8 * LDA]);
            a[mt][2] = f2u(p[4]); a[mt][3] = f2u(p[8 * LDA + 4]);
        }
        #pragma unroll
        for (int nt = 0; nt < NTN; ++nt) {
            const float* p = sB + (wn * (NTN * 8) + nt * 8 + g) * LDA + kk + t4;
            b[nt][0] = f2u(p[0]); b[nt][1] = f2u(p[4]);
        }
        #pragma unroll
        for (int mt = 0; mt < 4; ++mt)
            #pragma unroll
            for (int nt = 0; nt < NTN; ++nt)
                MMA8(c[mt][nt], a[mt], b[nt]);
    }
}

template<int RB, int NTN, int BF4B>
static __device__ __forceinline__ void gemm_loop(const float* __restrict__ Ag, int lda,
    const float* __restrict__ Bg, int ldb, int NT, float* sm, float c[][NTN][4],
    int tid, int wm, int wn, int g, int t4)
{
    const int stageF = (128 + RB) * LDA;
    float* sA0 = sm;               float* sB0 = sm + 128 * LDA;
    float* sA1 = sm + stageF;      float* sB1 = sm + stageF + 128 * LDA;

    #pragma unroll
    for (int i = 0; i < 4; ++i) {
        int idx = tid + i * 256, r = idx >> 3, c4 = (idx & 7) * 4;
        sts4(sA0 + r * LDA + c4, *(const float4*)(Ag + (size_t)r * lda + c4));
    }
    #pragma unroll
    for (int i = 0; i < BF4B; ++i) {
        int idx = tid + i * 256, r = idx >> 3, c4 = (idx & 7) * 4;
        sts4(sB0 + r * LDA + c4, *(const float4*)(Bg + (size_t)r * ldb + c4));
    }
    __syncthreads();

    for (int t = 0; t < NT; ++t) {
        float* sA = (t & 1) ? sA1 : sA0;
        float* sB = (t & 1) ? sB1 : sB0;
        float4 pa[4], pb[BF4B];
        const bool more = (t + 1 < NT);
        if (more) {
            const int kt = (t + 1) * 32;
            #pragma unroll
            for (int i = 0; i < 4; ++i) {
                int idx = tid + i * 256, r = idx >> 3, c4 = (idx & 7) * 4;
                pa[i] = *(const float4*)(Ag + (size_t)r * lda + kt + c4);
            }
            #pragma unroll
            for (int i = 0; i < BF4B; ++i) {
                int idx = tid + i * 256, r = idx >> 3, c4 = (idx & 7) * 4;
                pb[i] = *(const float4*)(Bg + (size_t)r * ldb + kt + c4);
            }
        }
        mma_tile<NTN>(sA, sB, wm, wn, g, t4, c);
        if (more) {
            float* dA = (t & 1) ? sA0 : sA1;
            float* dB = (t & 1) ? sB0 : sB1;
            #pragma unroll
            for (int i = 0; i < 4; ++i) {
                int idx = tid + i * 256, r = idx >> 3, c4 = (idx & 7) * 4;
                sts4(dA + r * LDA + c4, pa[i]);
            }
            #pragma unroll
            for (int i = 0; i < BF4B; ++i) {
                int idx = tid + i * 256, r = idx >> 3, c4 = (idx & 7) * 4;
                sts4(dB + r * LDA + c4, pb[i]);
            }
        }
        __syncthreads();
    }
}

template<int NTN, int P>
static __device__ __forceinline__ void frag_to_epi(float* epi, float c[][NTN][4],
    int wm, int wn, int g, int t4)
{
    #pragma unroll
    for (int mt = 0; mt < 4; ++mt)
        #pragma unroll
        for (int nt = 0; nt < NTN; ++nt) {
            int r = wm * 64 + mt * 16 + g;
            int cc = wn * (NTN * 8) + nt * 8 + t4 * 2;
            *(float2*)&epi[r * P + cc]       = make_float2(c[mt][nt][0], c[mt][nt][1]);
            *(float2*)&epi[(r + 8) * P + cc] = make_float2(c[mt][nt][2], c[mt][nt][3]);
        }
}

// ---------------------------------------------------------------------------
// Projections: relu(A @ W^T + b). MODE 0->g_qh 1->g_kh 2->g_vt 3: g_o->outp
// ---------------------------------------------------------------------------
template<int MODE>
__global__ void __launch_bounds__(256)
proj_tc(const float* __restrict__ A, const float* __restrict__ W,
        const float* __restrict__ bias, float* __restrict__ outp)
{
    extern __shared__ float sm[];
    const int tid = threadIdx.x, wid = tid >> 5, lane = tid & 31;
    const int wm = wid >> 2, wn = wid & 3, g = lane >> 2, t4 = lane & 3;
    const int n0 = blockIdx.x * 128, m0 = blockIdx.y * 128;
    const float* Ap = (MODE == 3) ? g_o : A;

    float c[4][4][4];
    #pragma unroll
    for (int i = 0; i < 4; ++i)
        #pragma unroll
        for (int j = 0; j < 4; ++j)
            #pragma unroll
            for (int e = 0; e < 4; ++e) c[i][j][e] = 0.f;

    gemm_loop<128, 4, 4>(Ap + (size_t)m0 * EE, EE, W + (size_t)n0 * EE, EE, 32,
                         sm, c, tid, wm, wn, g, t4);

    float* epi = sm;
    frag_to_epi<4, 132>(epi, c, wm, wn, g, t4);
    __syncthreads();

    const int bidx = m0 >> 11, l0 = m0 & (LL - 1);
    if (MODE == 2) {
        const int bh0 = bidx * NH + (n0 >> 6);
        for (int idx = tid; idx < 128 * 128; idx += 256) {
            int r = idx & 127, cc = idx >> 7;
            float v = tf32f(fmaxf(epi[r * 132 + cc] + __ldg(bias + n0 + cc), 0.f));
            g_vt[((size_t)(bh0 + (cc >> 6)) * HDD + (cc & 63)) * LL + l0 + r] = v;
        }
    } else {
        for (int idx = tid; idx < 128 * 32; idx += 256) {
            int r = idx >> 5, cc = (idx & 31) * 4;
            int n = n0 + cc;
            float4 v = *(float4*)&epi[r * 132 + cc];
            v.x = fmaxf(v.x + __ldg(bias + n),     0.f);
            v.y = fmaxf(v.y + __ldg(bias + n + 1), 0.f);
            v.z = fmaxf(v.z + __ldg(bias + n + 2), 0.f);
            v.w = fmaxf(v.w + __ldg(bias + n + 3), 0.f);
            if (MODE == 3) {
                *(float4*)(outp + (size_t)(m0 + r) * DD + n) = v;
            } else {
                v.x = tf32f(v.x); v.y = tf32f(v.y); v.z = tf32f(v.z); v.w = tf32f(v.w);
                float* dst = ((MODE == 0) ? g_qh : g_kh) +
                    (((size_t)(bidx * NH + (n >> 6))) * LL + l0 + r) * HDD + (n & 63);
                *(float4*)dst = v;
            }
        }
    }
}

// ---------------------------------------------------------------------------
// Flash v5: 128 threads, q-tile 64, K-tile 32, smem 54.8KB -> 4 CTAs/SM
// (regs pinned to 128 by launch_bounds; 128*128*4 = 64K = RF exactly).
// Aliasing: band <- rkT (dead after prologue); rv loaded into p_s region
// in the epilogue (p_s dead after loop); epi staging <- buf0.
// ---------------------------------------------------------------------------
#define F_SK0   0        // 32*68 = 2176
#define F_SV0   2176     // 64*36 = 2304
#define F_SK1   4480     // 2176  (sQ aliases SK1+SV1 during prologue)
#define F_SV1   6656     // 2304
#define F_SQ    4480     // 64*68 = 4352 (prologue only; fits 4480..8960)
#define F_PS    8960     // 64*36 = 2304 (loop); rv (33*64=2112) in epilogue
#define F_RKT   11264    // 64*34 = 2176 (prologue); band (64*31=1984) in loop
#define F_BAND  11264
#define F_LROW  13440    // 64
#define F_LO    13504
#define F_HI    13568
#define F_MROW  13632
#define FLASH_SMEM (13696 * 4)   // 54,784 B -> 4 CTAs/SM

__global__ void __launch_bounds__(128, 4)
flash_tc(const float* __restrict__ rel_k, const float* __restrict__ rel_v)
{
    extern __shared__ float sm[];
    float* p_s  = sm + F_PS;
    float* band = sm + F_BAND;
    float* rkT  = sm + F_RKT;
    float* l_row  = sm + F_LROW;
    float* lo_row = sm + F_LO;
    float* hi_row = sm + F_HI;
    float* m_row  = sm + F_MROW;

    const int tid = threadIdx.x, wid = tid >> 5, lane = tid & 31;
    const int g = lane >> 2, t4 = lane & 3;
    const int q0 = blockIdx.x * 64, bh = blockIdx.y;

    const float* Kg = g_kh + (size_t)bh * LL * HDD;
    const float* Vg = g_vt + (size_t)bh * HDD * LL;

    const int krow = tid >> 4, kc4 = (tid & 15) * 4;
    const int vrow = tid >> 3, vc4 = (tid & 7) * 4;

    // KV tile 0 -> buf0 (doesn't touch sQ region)
    #pragma unroll
    for (int i = 0; i < 4; ++i) {
        int rr = krow + i * 8;
        CP16(sm + F_SK0 + rr * 68 + kc4, Kg + (size_t)rr * HDD + kc4);
        int vr = vrow + i * 16;
        CP16(sm + F_SV0 + vr * 36 + vc4, Vg + (size_t)vr * LL + vc4);
    }
    CP_COMMIT();

    // prologue: sQ (aliases buf1), rkT
    float* sQ = sm + F_SQ;
    const float* Qg = g_qh + ((size_t)bh * LL + q0) * HDD;
    #pragma unroll
    for (int i = 0; i < 8; ++i) {
        int rr = krow + i * 8;
        *(float4*)(sQ + rr * 68 + kc4) = *(const float4*)(Qg + (size_t)rr * HDD + kc4);
    }
    for (int idx = tid; idx < NDD * HDD; idx += 128) {
        int j = idx >> 6, d = idx & 63;
        rkT[d * 34 + j] = rel_k[idx];
    }
    __syncthreads();

    // p_s[r][j] = sQ[r] . rel_k[j]
    for (int idx = tid; idx < 64 * NDD; idx += 128) {
        int r = idx / 33, j = idx - r * 33;
        float s = 0.f;
        #pragma unroll
        for (int d = 0; d < HDD; ++d) s = fmaf(sQ[r * 68 + d], rkT[d * 34 + j], s);
        p_s[r * 36 + j] = s;
    }

    // Q fragments (loop-invariant): rows wid*16+g / +8
    uint32_t qa[8][4];
    {
        const float* qp = sQ + (wid * 16 + g) * 68 + t4;
        #pragma unroll
        for (int ks = 0; ks < 8; ++ks) {
            qa[ks][0] = f2u(qp[ks * 8]);
            qa[ks][1] = f2u(qp[8 * 68 + ks * 8]);
            qa[ks][2] = f2u(qp[ks * 8 + 4]);
            qa[ks][3] = f2u(qp[8 * 68 + ks * 8 + 4]);
        }
    }
    __syncthreads();   // all rkT reads done -> band may overwrite rkT region

    for (int idx = tid; idx < 64 * 31; idx += 128) band[idx] = -1e30f;
    CP_WAIT0();
    __syncthreads();   // buf0 ready; band init visible; sQ may be overwritten

    float m_r[2] = { -1e30f, -1e30f }, l_r[2] = { 0.f, 0.f };
    float lo_r[2] = { 0.f, 0.f }, hi_r[2] = { 0.f, 0.f };
    float c_o[8][4];
    #pragma unroll
    for (int nt = 0; nt < 8; ++nt)
        #pragma unroll
        for (int e = 0; e < 4; ++e) c_o[nt][e] = 0.f;

    for (int kt = 0; kt < 64; ++kt) {
        const int cur = kt & 1;
        const float* sK = sm + (cur ? F_SK1 : F_SK0);
        const float* sV = sm + (cur ? F_SV1 : F_SV0);
        if (kt + 1 < 64) {
            float* dK = sm + (cur ? F_SK0 : F_SK1);
            float* dV = sm + (cur ? F_SV0 : F_SV1);
            #pragma unroll
            for (int i = 0; i < 2; ++i) {
                int rr = krow + i * 8;
                CP16(dK + rr * 68 + kc4, Kg + (size_t)((kt + 1) * 32 + rr) * HDD + kc4);
                CP16(dK + (rr + 16) * 68 + kc4, Kg + (size_t)((kt + 1) * 32 + rr + 16) * HDD + kc4);
                int vr = vrow + i * 16;
                CP16(dV + vr * 36 + vc4, Vg + (size_t)vr * LL + (kt + 1) * 32 + vc4);
                CP16(dV + (vr + 32) * 36 + vc4, Vg + (size_t)(vr + 32) * LL + (kt + 1) * 32 + vc4);
            }
            CP_COMMIT();
        }

        // GEMM1: S(16q x 32k) per warp, Q from registers
        float cs[4][4];
        #pragma unroll
        for (int nt = 0; nt < 4; ++nt)
            #pragma unroll
            for (int e = 0; e < 4; ++e) cs[nt][e] = 0.f;
        #pragma unroll
        for (int ks = 0; ks < 8; ++ks) {
            const int kk = ks * 8;
            #pragma unroll
            for (int nt = 0; nt < 4; ++nt) {
                const float* bp = sK + (nt * 8 + g) * 68 + kk + t4;
                uint32_t b[2] = { f2u(bp[0]), f2u(bp[4]) };
                MMA8(cs[nt], qa[ks], b);
            }
        }

        // online softmax (warp-local); P written back into cs (tf32)
        float alpha01[2];
        #pragma unroll
        for (int rr = 0; rr < 2; ++rr) {
            const int r = wid * 16 + g + rr * 8;
            const int qg = q0 + r;
            float sv[4][2], mx = -1e30f;
            #pragma unroll
            for (int nt = 0; nt < 4; ++nt)
                #pragma unroll
                for (int e = 0; e < 2; ++e) {
                    int kg = kt * 32 + nt * 8 + t4 * 2 + e;
                    int d = kg - qg;
                    int j = d < -16 ? -16 : (d > 16 ? 16 : d);
                    float v = (cs[nt][rr * 2 + e] + p_s[r * 36 + j + 16]) * SCALE;
                    sv[nt][e] = v;
                    mx = fmaxf(mx, v);
                }
            mx = fmaxf(mx, __shfl_xor_sync(0xffffffffu, mx, 1));
            mx = fmaxf(mx, __shfl_xor_sync(0xffffffffu, mx, 2));
            float mnew = fmaxf(m_r[rr], mx);
            float alpha = __expf(m_r[rr] - mnew);
            m_r[rr] = mnew;
            alpha01[rr] = alpha;
            l_r[rr] *= alpha; lo_r[rr] *= alpha; hi_r[rr] *= alpha;
            float sum = 0.f, slo = 0.f, shi = 0.f;
            #pragma unroll
            for (int nt = 0; nt < 4; ++nt)
                #pragma unroll
                for (int e = 0; e < 2; ++e) {
                    int kg = kt * 32 + nt * 8 + t4 * 2 + e;
                    int d = kg - qg;
                    float p = __expf(sv[nt][e] - mnew);
                    sum += p;
                    if (d <= -16) slo += p;
                    else if (d >= 16) shi += p;
                    else band[r * 31 + d + 15] = sv[nt][e];   // raw score
                    cs[nt][rr * 2 + e] = tf32f(p);
                }
            sum += __shfl_xor_sync(0xffffffffu, sum, 1);
            sum += __shfl_xor_sync(0xffffffffu, sum, 2);
            slo += __shfl_xor_sync(0xffffffffu, slo, 1);
            slo += __shfl_xor_sync(0xffffffffu, slo, 2);
            shi += __shfl_xor_sync(0xffffffffu, shi, 1);
            shi += __shfl_xor_sync(0xffffffffu, shi, 2);
            l_r[rr] += sum; lo_r[rr] += slo; hi_r[rr] += shi;
        }

        // rescale output accumulator (warp-local alphas)
        #pragma unroll
        for (int nt = 0; nt < 8; ++nt) {
            c_o[nt][0] *= alpha01[0]; c_o[nt][1] *= alpha01[0];
            c_o[nt][2] *= alpha01[1]; c_o[nt][3] *= alpha01[1];
        }

        // GEMM2: O(16q x 64d) per warp; P repacked from cs via shuffles
        const int sl1 = (lane & ~3) | (t4 >> 1);
        const int sl2 = sl1 + 2;
        const bool odd = (t4 & 1);
        #pragma unroll
        for (int kc = 0; kc < 4; ++kc) {
            float x0 = __shfl_sync(0xffffffffu, cs[kc][0], sl1);
            float x1 = __shfl_sync(0xffffffffu, cs[kc][1], sl1);
            float x2 = __shfl_sync(0xffffffffu, cs[kc][2], sl1);
            float x3 = __shfl_sync(0xffffffffu, cs[kc][3], sl1);
            float y0 = __shfl_sync(0xffffffffu, cs[kc][0], sl2);
            float y1 = __shfl_sync(0xffffffffu, cs[kc][1], sl2);
            float y2 = __shfl_sync(0xffffffffu, cs[kc][2], sl2);
            float y3 = __shfl_sync(0xffffffffu, cs[kc][3], sl2);
            uint32_t a[4] = { f2u(odd ? x1 : x0), f2u(odd ? x3 : x2),
                              f2u(odd ? y1 : y0), f2u(odd ? y3 : y2) };
            const int kk = kc * 8;
            #pragma unroll
            for (int nd = 0; nd < 8; ++nd) {
                const float* bp = sV + (nd * 8 + g) * 36 + kk + t4;
                uint32_t b[2] = { f2u(bp[0]), f2u(bp[4]) };
                MMA8(c_o[nd], a, b);
            }
        }

        if (kt + 1 < 64) CP_WAIT0();
        __syncthreads();
    }

    // publish per-row state
    #pragma unroll
    for (int rr = 0; rr < 2; ++rr) {
        int r = wid * 16 + g + rr * 8;
        if (t4 == 0) {
            l_row[r] = l_r[rr]; lo_row[r] = lo_r[rr];
            hi_row[r] = hi_r[rr]; m_row[r] = m_r[rr];
        }
    }

    // stage c_o into epi (aliases buf0; safe after final sync) and load rv
    // into the now-dead p_s region
    float* epi = sm;
    float* rvs = p_s;
    {
        int r = wid * 16 + g;
        #pragma unroll
        for (int nd = 0; nd < 8; ++nd) {
            int cc = nd * 8 + t4 * 2;
            *(float2*)&epi[r * 68 + cc]       = make_float2(c_o[nd][0], c_o[nd][1]);
            *(float2*)&epi[(r + 8) * 68 + cc] = make_float2(c_o[nd][2], c_o[nd][3]);
        }
    }
    for (int idx = tid; idx < NDD * HDD; idx += 128) rvs[idx] = rel_v[idx];
    __syncthreads();

    // epilogue: normalize + rel_v terms, write merged-head g_o
    const int bidx = bh >> 4, h = bh & 15;
    for (int idx = tid; idx < 64 * 16; idx += 128) {
        int r = idx >> 4, cc = (idx & 15) * 4;
        float linv = 1.f / l_row[r];
        float mfin = m_row[r];
        float w0 = lo_row[r] * linv, w32 = hi_row[r] * linv;
        float4 acc = *(float4*)&epi[r * 68 + cc];
        acc.x *= linv; acc.y *= linv; acc.z *= linv; acc.w *= linv;
        const float* rv0 = rvs + cc;
        const float* rv32 = rvs + 32 * HDD + cc;
        acc.x += w0 * rv0[0] + w32 * rv32[0];
        acc.y += w0 * rv0[1] + w32 * rv32[1];
        acc.z += w0 * rv0[2] + w32 * rv32[2];
        acc.w += w0 * rv0[3] + w32 * rv32[3];
        for (int j = 0; j < 31; ++j) {
            float bw = __expf(band[r * 31 + j] - mfin) * linv;
            const float* rj = rvs + (j + 1) * HDD + cc;
            acc.x = fmaf(bw, rj[0], acc.x);
            acc.y = fmaf(bw, rj[1], acc.y);
            acc.z = fmaf(bw, rj[2], acc.z);
            acc.w = fmaf(bw, rj[3], acc.w);
        }
        *(float4*)&g_o[((size_t)bidx * LL + q0 + r) * DD + h * HDD + cc] = acc;
    }
}

// ---------------------------------------------------------------------------
extern "C" void kernel_launch(void* const* d_in, const int* in_sizes, int n_in,
                              void* d_out, int out_size) {
    const float* q     = (const float*)d_in[0];
    const float* k     = (const float*)d_in[1];
    const float* v     = (const float*)d_in[2];
    const float* Wq    = (const float*)d_in[3];
    const float* bq    = (const float*)d_in[4];
    const float* Wk    = (const float*)d_in[5];
    const float* bk    = (const float*)d_in[6];
    const float* Wv    = (const float*)d_in[7];
    const float* bv    = (const float*)d_in[8];
    const float* Wo    = (const float*)d_in[9];
    const float* bo    = (const float*)d_in[10];
    const float* rel_k = (const float*)d_in[11];
    const float* rel_v = (const float*)d_in[12];
    float* out = (float*)d_out;

    cudaFuncSetAttribute(proj_tc<0>, cudaFuncAttributeMaxDynamicSharedMemorySize, SMEM_BYTES);
    cudaFuncSetAttribute(proj_tc<1>, cudaFuncAttributeMaxDynamicSharedMemorySize, SMEM_BYTES);
    cudaFuncSetAttribute(proj_tc<2>, cudaFuncAttributeMaxDynamicSharedMemorySize, SMEM_BYTES);
    cudaFuncSetAttribute(proj_tc<3>, cudaFuncAttributeMaxDynamicSharedMemorySize, SMEM_BYTES);
    cudaFuncSetAttribute(flash_tc,   cudaFuncAttributeMaxDynamicSharedMemorySize, FLASH_SMEM);

    dim3 gproj(DD / 128, MLL / 128);
    proj_tc<0><<<gproj, 256, SMEM_BYTES>>>(q, Wq, bq, nullptr);
    proj_tc<1><<<gproj, 256, SMEM_BYTES>>>(k, Wk, bk, nullptr);
    proj_tc<2><<<gproj, 256, SMEM_BYTES>>>(v, Wv, bv, nullptr);

    flash_tc<<<dim3(LL / 64, BHH), 128, FLASH_SMEM>>>(rel_k, rel_v);

    proj_tc<3><<<gproj, 256, SMEM_BYTES>>>(nullptr, Wo, bo, out);
}